// round 8
// baseline (speedup 1.0000x reference)
#include <cuda_runtime.h>
#include <math.h>

#define BB   64
#define SIN  512
#define TOUT 64
#define HDIM 1024
#define VDIM 1024
#define GDIM 3072   // 3*HDIM
#define NBLK 128    // persistent-kernel grid size (co-resident, divides all phases)

static const long OFF_HID = (long)BB*TOUT*VDIM;        // 4194304
static const long OFF_ATT = OFF_HID + 2L*BB*HDIM;      // 4325376

// ---------------- persistent scratch (device globals; no allocs) ----------------
__device__ float g_y0 [BB*SIN*HDIM];     // encoder layer-0 outputs   (134 MB)
__device__ float g_xp1[(long)BB*SIN*GDIM]; // precomputed y0 @ Wih1^T (402 MB)
__device__ float g_enc[BB*SIN*HDIM];     // encoder layer-1 outputs   (134 MB)
__device__ float g_h  [2][BB*HDIM];      // running hidden states
__device__ float g_part[8*BB*GDIM];      // split-K GEMM partials     (6.3 MB)
__device__ float g_q  [BB*HDIM];
__device__ float g_att[BB*HDIM];
__device__ float g_l1 [BB*HDIM];
__device__ float g_scores[BB*SIN];
__device__ float g_aw [BB*SIN];
__device__ int   g_tok[BB];

// ---------------- software grid barrier (self-resetting; replay-safe) -----------
__device__ unsigned g_cnt = 0;
__device__ unsigned g_gen = 0;

__device__ __forceinline__ void grid_sync() {
    __syncthreads();
    if (threadIdx.x == 0) {
        __threadfence();
        unsigned gen = *(volatile unsigned*)&g_gen;
        if (atomicAdd(&g_cnt, 1u) == (unsigned)gridDim.x - 1u) {
            g_cnt = 0;
            __threadfence();
            atomicAdd(&g_gen, 1u);
        } else {
            while (*(volatile unsigned*)&g_gen == gen) __nanosleep(32);
        }
        __threadfence();
    }
    __syncthreads();
}

// ---------------- init (runs every launch) ----------------
__global__ void k_init() {
    int i = blockIdx.x*256 + threadIdx.x;      // 65536 threads
    g_h[0][i] = 0.f; g_h[1][i] = 0.f;
    if (i == 0) g_cnt = 0;
    if (i < BB) g_tok[i] = 0;
}

// ---------------- one 64x64xKlen tile: Cz[0:64, n0:n0+64] = A[:,k0:] * B[:,k0:]^T
__device__ __forceinline__ void tile_mm(
    const float* __restrict__ A, long lda, const int* __restrict__ idx,
    const float* __restrict__ B, long ldb,
    int k0, int Klen, int n0, float* __restrict__ Cz, int N,
    float (&As)[16][68], float (&Bs)[16][68])
{
    const int tid = threadIdx.x;
    const int lr  = tid >> 2;
    const int lc  = (tid & 3) << 2;
    const int ty4 = (tid >> 4) << 2;
    const int tx4 = (tid & 15) << 2;

    long arow = idx ? (long)idx[lr]*lda : (long)lr*lda;
    const float* Ap = A + arow + k0 + lc;
    const float* Bp = B + (long)(n0 + lr)*ldb + k0 + lc;

    float acc[4][4] = {};
    float4 av = *(const float4*)Ap;
    float4 bv = *(const float4*)Bp;

    for (int kt = 0; kt < Klen; kt += 16) {
        As[lc+0][lr]=av.x; As[lc+1][lr]=av.y; As[lc+2][lr]=av.z; As[lc+3][lr]=av.w;
        Bs[lc+0][lr]=bv.x; Bs[lc+1][lr]=bv.y; Bs[lc+2][lr]=bv.z; Bs[lc+3][lr]=bv.w;
        __syncthreads();
        if (kt + 16 < Klen) {
            av = *(const float4*)(Ap + kt + 16);
            bv = *(const float4*)(Bp + kt + 16);
        }
        #pragma unroll
        for (int k = 0; k < 16; k++) {
            float4 a = *(const float4*)&As[k][ty4];
            float4 b = *(const float4*)&Bs[k][tx4];
            acc[0][0]+=a.x*b.x; acc[0][1]+=a.x*b.y; acc[0][2]+=a.x*b.z; acc[0][3]+=a.x*b.w;
            acc[1][0]+=a.y*b.x; acc[1][1]+=a.y*b.y; acc[1][2]+=a.y*b.z; acc[1][3]+=a.y*b.w;
            acc[2][0]+=a.z*b.x; acc[2][1]+=a.z*b.y; acc[2][2]+=a.z*b.z; acc[2][3]+=a.z*b.w;
            acc[3][0]+=a.w*b.x; acc[3][1]+=a.w*b.y; acc[3][2]+=a.w*b.z; acc[3][3]+=a.w*b.w;
        }
        __syncthreads();
    }
    float* Cp = Cz + (long)ty4*N + n0 + tx4;
    #pragma unroll
    for (int i = 0; i < 4; i++)
        *(float4*)(Cp + (long)i*N) = make_float4(acc[i][0],acc[i][1],acc[i][2],acc[i][3]);
}

// ---------------- persistent encoder GRU scan (one layer, all 512 steps) --------
__global__ __launch_bounds__(256,2) void enc_scan(
    int layer, const float* __restrict__ x,
    const float* __restrict__ Wih,
    const float* __restrict__ Whh,
    const float* __restrict__ bih, const float* __restrict__ bhh)
{
    __shared__ float As[16][68], Bs[16][68];
    float* h = g_h[layer];
    const int nthr = gridDim.x * blockDim.x;
    const int gtid = blockIdx.x * blockDim.x + threadIdx.x;

    for (int t = 0; t < SIN; t++) {
        // GEMM phase: h @ Whh^T into 8 split-K partials; 384 tiles, 3 per block
        for (int tile = blockIdx.x; tile < 384; tile += gridDim.x) {
            int z = tile / 48, nt = tile % 48;
            tile_mm(h, 1024, (const int*)0, Whh, 1024, z*128, 128, nt*64,
                    g_part + (long)z*64*GDIM, GDIM, As, Bs);
        }
        grid_sync();
        // gate phase
        for (int i = gtid; i < BB*HDIM; i += nthr) {
            int b = i >> 10, hh = i & 1023;
            float xr, xz, xn;
            if (layer == 0) {
                float x0 = x[(b*2  )*SIN + t];
                float x1 = x[(b*2+1)*SIN + t];
                xr = x0*Wih[2*hh]          + x1*Wih[2*hh+1]          + bih[hh];
                xz = x0*Wih[2*(HDIM+hh)]   + x1*Wih[2*(HDIM+hh)+1]   + bih[HDIM+hh];
                xn = x0*Wih[2*(2*HDIM+hh)] + x1*Wih[2*(2*HDIM+hh)+1] + bih[2*HDIM+hh];
            } else {
                const float* xp = g_xp1 + (long)(b*SIN + t)*GDIM;
                xr = xp[hh]        + bih[hh];
                xz = xp[HDIM+hh]   + bih[HDIM+hh];
                xn = xp[2*HDIM+hh] + bih[2*HDIM+hh];
            }
            float hr = bhh[hh], hz = bhh[HDIM+hh], hn = bhh[2*HDIM+hh];
            #pragma unroll
            for (int zp = 0; zp < 8; zp++) {
                const float* p = g_part + (long)(zp*64 + b)*GDIM;
                hr += p[hh]; hz += p[HDIM+hh]; hn += p[2*HDIM+hh];
            }
            float r  = 1.f/(1.f + expf(-(xr+hr)));
            float zg = 1.f/(1.f + expf(-(xz+hz)));
            float n  = tanhf(xn + r*hn);
            float hnew = (1.f - zg)*n + zg*h[i];
            h[i] = hnew;
            float* dst = (layer == 0) ? g_y0 : g_enc;
            dst[(long)(b*SIN + t)*HDIM + hh] = hnew;
        }
        grid_sync();
    }
}

// ---------------- big GEMM: xp1[32768,3072] = y0[32768,1024] @ Wih1[3072,1024]^T
__global__ __launch_bounds__(256) void gemm_big(
    const float* __restrict__ A, const float* __restrict__ B,
    float* __restrict__ C, int N, int K)
{
    __shared__ float As[16][68], Bs[16][68];
    const int m0 = blockIdx.y * 64, n0 = blockIdx.x * 64;
    const int tid = threadIdx.x;
    const int lr  = tid >> 2, lc = (tid & 3) << 2;
    const int ty4 = (tid >> 4) << 2, tx4 = (tid & 15) << 2;

    const float* Ap = A + (long)(m0 + lr)*K + lc;
    const float* Bp = B + (long)(n0 + lr)*K + lc;

    float acc[4][4] = {};
    float4 av = *(const float4*)Ap;
    float4 bv = *(const float4*)Bp;

    for (int kt = 0; kt < K; kt += 16) {
        As[lc+0][lr]=av.x; As[lc+1][lr]=av.y; As[lc+2][lr]=av.z; As[lc+3][lr]=av.w;
        Bs[lc+0][lr]=bv.x; Bs[lc+1][lr]=bv.y; Bs[lc+2][lr]=bv.z; Bs[lc+3][lr]=bv.w;
        __syncthreads();
        if (kt + 16 < K) {
            av = *(const float4*)(Ap + kt + 16);
            bv = *(const float4*)(Bp + kt + 16);
        }
        #pragma unroll
        for (int k = 0; k < 16; k++) {
            float4 a = *(const float4*)&As[k][ty4];
            float4 b = *(const float4*)&Bs[k][tx4];
            acc[0][0]+=a.x*b.x; acc[0][1]+=a.x*b.y; acc[0][2]+=a.x*b.z; acc[0][3]+=a.x*b.w;
            acc[1][0]+=a.y*b.x; acc[1][1]+=a.y*b.y; acc[1][2]+=a.y*b.z; acc[1][3]+=a.y*b.w;
            acc[2][0]+=a.z*b.x; acc[2][1]+=a.z*b.y; acc[2][2]+=a.z*b.z; acc[2][3]+=a.z*b.w;
            acc[3][0]+=a.w*b.x; acc[3][1]+=a.w*b.y; acc[3][2]+=a.w*b.z; acc[3][3]+=a.w*b.w;
        }
        __syncthreads();
    }
    float* Cp = C + (long)(m0 + ty4)*N + n0 + tx4;
    #pragma unroll
    for (int i = 0; i < 4; i++)
        *(float4*)(Cp + (long)i*N) = make_float4(acc[i][0],acc[i][1],acc[i][2],acc[i][3]);
}

// ---------------- persistent decoder: all 64 greedy autoregressive steps --------
__global__ __launch_bounds__(256,2) void dec_scan(
    const float* __restrict__ emb,
    const float* __restrict__ dWih0, const float* __restrict__ dWhh0,
    const float* __restrict__ dbih0, const float* __restrict__ dbhh0,
    const float* __restrict__ dWih1, const float* __restrict__ dWhh1,
    const float* __restrict__ dbih1, const float* __restrict__ dbhh1,
    const float* __restrict__ hqW,  const float* __restrict__ hqb,
    const float* __restrict__ combW,const float* __restrict__ combb,
    const float* __restrict__ fcW,  const float* __restrict__ fcb,
    float* __restrict__ out, float* __restrict__ outAtt)
{
    __shared__ float As[16][68], Bs[16][68];
    const int tid  = threadIdx.x;
    const int nthr = gridDim.x * blockDim.x;
    const int gtid = blockIdx.x * blockDim.x + tid;
    float* h0 = g_h[0];
    float* h1 = g_h[1];

    for (int t = 0; t < TOUT; t++) {
        // ---- layer 0 GEMM: emb[tok]@Wih0^T (z 0..3) + h0@Whh0^T (z 4..7) ----
        for (int tile = blockIdx.x; tile < 128; tile += gridDim.x) {
            int z = tile >> 4, nt = tile & 15;
            if (z < 4)
                tile_mm(emb, 1024, g_tok, dWih0, 1024, z*256, 256, nt*64,
                        g_part + (long)z*64*1024, 1024, As, Bs);
            else
                tile_mm(h0, 1024, (const int*)0, dWhh0, 1024, (z-4)*256, 256, nt*64,
                        g_part + (long)z*64*1024, 1024, As, Bs);
        }
        grid_sync();
        for (int i = gtid; i < BB*HDIM; i += nthr) {
            int b = i >> 10, n = i & 1023;
            float s = dbih0[n] + dbhh0[n];
            #pragma unroll
            for (int z = 0; z < 8; z++) s += g_part[(long)(z*64 + b)*1024 + n];
            h0[i] = tanhf(s);
        }
        grid_sync();
        // ---- layer 1 GEMM ----
        for (int tile = blockIdx.x; tile < 128; tile += gridDim.x) {
            int z = tile >> 4, nt = tile & 15;
            if (z < 4)
                tile_mm(h0, 1024, (const int*)0, dWih1, 1024, z*256, 256, nt*64,
                        g_part + (long)z*64*1024, 1024, As, Bs);
            else
                tile_mm(h1, 1024, (const int*)0, dWhh1, 1024, (z-4)*256, 256, nt*64,
                        g_part + (long)z*64*1024, 1024, As, Bs);
        }
        grid_sync();
        for (int i = gtid; i < BB*HDIM; i += nthr) {
            int b = i >> 10, n = i & 1023;
            float s = dbih1[n] + dbhh1[n];
            #pragma unroll
            for (int z = 0; z < 8; z++) s += g_part[(long)(z*64 + b)*1024 + n];
            h1[i] = tanhf(s);
        }
        grid_sync();
        // ---- q = h1 @ hqW^T + hqb ----
        for (int tile = blockIdx.x; tile < 128; tile += gridDim.x) {
            int z = tile >> 4, nt = tile & 15;
            tile_mm(h1, 1024, (const int*)0, hqW, 1024, z*128, 128, nt*64,
                    g_part + (long)z*64*1024, 1024, As, Bs);
        }
        grid_sync();
        for (int i = gtid; i < BB*HDIM; i += nthr) {
            int b = i >> 10, n = i & 1023;
            float s = hqb[n];
            #pragma unroll
            for (int z = 0; z < 8; z++) s += g_part[(long)(z*64 + b)*1024 + n];
            g_q[i] = s;
        }
        grid_sync();
        // ---- scores[b,s] = enc[b,s,:] . q[b]  (1024 units, 8 per block) ----
        for (int u = blockIdx.x; u < 1024; u += gridDim.x) {
            int b = u >> 4, sc = u & 15;
            float* qs = &As[0][0];           // 1024 floats (fits in As)
            __syncthreads();
            for (int j = tid; j < HDIM; j += 256) qs[j] = g_q[b*HDIM + j];
            __syncthreads();
            int sl = tid >> 3, kp = tid & 7;
            int s  = sc*32 + sl;
            const float* e = g_enc + (long)(b*SIN + s)*HDIM;
            float acc = 0.f;
            #pragma unroll 4
            for (int i2 = 0; i2 < 32; i2++) {
                int k = i2*32 + kp*4;
                float4 ev = *(const float4*)(e + k);
                acc += ev.x*qs[k] + ev.y*qs[k+1] + ev.z*qs[k+2] + ev.w*qs[k+3];
            }
            acc += __shfl_xor_sync(0xffffffffu, acc, 4);
            acc += __shfl_xor_sync(0xffffffffu, acc, 2);
            acc += __shfl_xor_sync(0xffffffffu, acc, 1);
            if (kp == 0) g_scores[b*SIN + s] = acc;
            __syncthreads();
        }
        grid_sync();
        // ---- softmax over s (blocks 0..63) ----
        if (blockIdx.x < 64) {
            int b = blockIdx.x;
            float* red = &As[0][0];
            float v0 = g_scores[b*SIN + tid], v1 = g_scores[b*SIN + 256 + tid];
            red[tid] = fmaxf(v0, v1); __syncthreads();
            for (int w = 128; w > 0; w >>= 1) {
                if (tid < w) red[tid] = fmaxf(red[tid], red[tid+w]);
                __syncthreads();
            }
            float mx = red[0]; __syncthreads();
            float e0 = expf(v0 - mx), e1 = expf(v1 - mx);
            red[tid] = e0 + e1; __syncthreads();
            for (int w = 128; w > 0; w >>= 1) {
                if (tid < w) red[tid] += red[tid+w];
                __syncthreads();
            }
            float inv = 1.f/red[0];
            float a0 = e0*inv, a1 = e1*inv;
            g_aw[b*SIN + tid] = a0; g_aw[b*SIN + 256 + tid] = a1;
            if (t == TOUT-1) { outAtt[b*SIN + tid] = a0; outAtt[b*SIN + 256 + tid] = a1; }
        }
        grid_sync();
        // ---- att[b,h] = sum_s aw[s]*enc[b,s,h]  (256 units, 2 per block) ----
        for (int u = blockIdx.x; u < 256; u += gridDim.x) {
            int hc = u & 3, b = u >> 2;
            float* aw = &As[0][0];           // 512 floats
            __syncthreads();
            for (int j = tid; j < SIN; j += 256) aw[j] = g_aw[b*SIN + j];
            __syncthreads();
            int hh = hc*256 + tid;
            const float* e = g_enc + (long)b*SIN*HDIM + hh;
            float acc = 0.f;
            #pragma unroll 8
            for (int s = 0; s < SIN; s++) acc += aw[s]*e[(long)s*HDIM];
            g_att[b*HDIM + hh] = acc;
            __syncthreads();
        }
        grid_sync();
        // ---- l1 = [h1|att] @ combW^T + combb  (combW is [1024, 2048]) ----
        for (int tile = blockIdx.x; tile < 128; tile += gridDim.x) {
            int z = tile >> 4, nt = tile & 15;
            if (z < 4)
                tile_mm(h1, 1024, (const int*)0, combW, 2048, z*256, 256, nt*64,
                        g_part + (long)z*64*1024, 1024, As, Bs);
            else
                tile_mm(g_att, 1024, (const int*)0, combW + 1024, 2048, (z-4)*256, 256, nt*64,
                        g_part + (long)z*64*1024, 1024, As, Bs);
        }
        grid_sync();
        for (int i = gtid; i < BB*HDIM; i += nthr) {
            int b = i >> 10, n = i & 1023;
            float s = combb[n];
            #pragma unroll
            for (int z = 0; z < 8; z++) s += g_part[(long)(z*64 + b)*1024 + n];
            g_l1[i] = s;
        }
        grid_sync();
        // ---- logits = l1 @ fcW^T + fcb -> out[:, t, :] ----
        for (int tile = blockIdx.x; tile < 128; tile += gridDim.x) {
            int z = tile >> 4, nt = tile & 15;
            tile_mm(g_l1, 1024, (const int*)0, fcW, 1024, z*128, 128, nt*64,
                    g_part + (long)z*64*1024, 1024, As, Bs);
        }
        grid_sync();
        for (int i = gtid; i < BB*VDIM; i += nthr) {
            int b = i >> 10, v = i & 1023;
            float s = fcb[v];
            #pragma unroll
            for (int z = 0; z < 8; z++) s += g_part[(long)(z*64 + b)*1024 + v];
            out[(long)(b*TOUT + t)*VDIM + v] = s;
        }
        grid_sync();
        // ---- argmax (first-max ties) -> g_tok; skip on last step ----
        if (t < TOUT-1) {
            if (blockIdx.x < 64) {
                int b = blockIdx.x;
                float* sv = &As[0][0];
                int*   si = (int*)&Bs[0][0];
                const float* l = out + (long)(b*TOUT + t)*VDIM;
                float best = -3.4e38f; int bi = 0;
                #pragma unroll
                for (int j = 0; j < 4; j++) {
                    int idx = tid*4 + j;
                    float v = l[idx];
                    if (v > best) { best = v; bi = idx; }
                }
                sv[tid] = best; si[tid] = bi; __syncthreads();
                for (int w = 128; w > 0; w >>= 1) {
                    if (tid < w) {
                        float v2 = sv[tid+w]; int i2 = si[tid+w];
                        if (v2 > sv[tid] || (v2 == sv[tid] && i2 < si[tid])) {
                            sv[tid] = v2; si[tid] = i2;
                        }
                    }
                    __syncthreads();
                }
                if (tid == 0) g_tok[b] = si[0];
            }
            grid_sync();
        }
    }
}

__global__ void k_copy_hidden(float* __restrict__ out) {   // 512 x 256
    int i = blockIdx.x*256 + threadIdx.x;
    out[i] = (&g_h[0][0])[i];
}

// ---------------- host ----------------
extern "C" void kernel_launch(void* const* d_in, const int* in_sizes, int n_in,
                              void* d_out, int out_size)
{
    (void)n_in; (void)out_size;
    // in_sizes[6]: signature order -> enc_Wih1 (3145728); dict order -> dec_Wih0 (1048576)
    bool sig = (in_sizes[6] == 3145728);
    const float* x   = (const float*)d_in[0];
    const float* emb = (const float*)d_in[1];
    const float *eWih0,*eWhh0,*ebih0,*ebhh0,*eWih1,*eWhh1,*ebih1,*ebhh1;
    const float *dWih0,*dWhh0,*dbih0,*dbhh0,*dWih1,*dWhh1,*dbih1,*dbhh1;
    if (sig) {
        eWih0=(const float*)d_in[2];  eWhh0=(const float*)d_in[3];
        ebih0=(const float*)d_in[4];  ebhh0=(const float*)d_in[5];
        eWih1=(const float*)d_in[6];  eWhh1=(const float*)d_in[7];
        ebih1=(const float*)d_in[8];  ebhh1=(const float*)d_in[9];
        dWih0=(const float*)d_in[10]; dWhh0=(const float*)d_in[11];
        dbih0=(const float*)d_in[12]; dbhh0=(const float*)d_in[13];
        dWih1=(const float*)d_in[14]; dWhh1=(const float*)d_in[15];
        dbih1=(const float*)d_in[16]; dbhh1=(const float*)d_in[17];
    } else {
        eWih0=(const float*)d_in[2];  eWhh0=(const float*)d_in[3];
        ebih0=(const float*)d_in[4];  ebhh0=(const float*)d_in[5];
        dWih0=(const float*)d_in[6];  dWhh0=(const float*)d_in[7];
        dbih0=(const float*)d_in[8];  dbhh0=(const float*)d_in[9];
        eWih1=(const float*)d_in[10]; eWhh1=(const float*)d_in[11];
        ebih1=(const float*)d_in[12]; ebhh1=(const float*)d_in[13];
        dWih1=(const float*)d_in[14]; dWhh1=(const float*)d_in[15];
        dbih1=(const float*)d_in[16]; dbhh1=(const float*)d_in[17];
    }
    const float* hq_W   = (const float*)d_in[18];
    const float* hq_b   = (const float*)d_in[19];
    const float* comb_W = (const float*)d_in[20];
    const float* comb_b = (const float*)d_in[21];
    const float* fc_W   = (const float*)d_in[22];
    const float* fc_b   = (const float*)d_in[23];
    float* out = (float*)d_out;

    float *p_y0, *p_xp1;
    cudaGetSymbolAddress((void**)&p_y0,  g_y0);
    cudaGetSymbolAddress((void**)&p_xp1, g_xp1);

    k_init<<<256,256>>>();

    // encoder layer 0 (512-step scan, one node)
    enc_scan<<<NBLK,256>>>(0, x, eWih0, eWhh0, ebih0, ebhh0);
    // xp1 = y0 @ Wih1^T (one big parallel GEMM)
    gemm_big<<<dim3(48,512),256>>>(p_y0, eWih1, p_xp1, GDIM, 1024);
    // encoder layer 1
    enc_scan<<<NBLK,256>>>(1, x, eWih1, eWhh1, ebih1, ebhh1);
    // decoder (64 greedy steps, one node)
    dec_scan<<<NBLK,256>>>(emb,
                           dWih0, dWhh0, dbih0, dbhh0,
                           dWih1, dWhh1, dbih1, dbhh1,
                           hq_W, hq_b, comb_W, comb_b, fc_W, fc_b,
                           out, out + OFF_ATT);
    // hidden [2, B, H]
    k_copy_hidden<<<512,256>>>(out + OFF_HID);
}

// round 9
// speedup vs baseline: 1.1753x; 1.1753x over previous
#include <cuda_runtime.h>
#include <math.h>

#define BB   64
#define SIN  512
#define TOUT 64
#define HDIM 1024
#define VDIM 1024
#define GDIM 3072   // 3*HDIM
#define NBLK 128    // persistent-kernel grid size (co-resident, divides all phases)

#define EPAD 68     // Ash row pad (floats)
#define BPAD 196    // Bsh row pad (floats)
// dynamic smem for enc_scan: Bsh[128][BPAD] + Ash[128][EPAD]
#define ENC_SMEM ((128*BPAD + 128*EPAD) * 4)

static const long OFF_HID = (long)BB*TOUT*VDIM;        // 4194304
static const long OFF_ATT = OFF_HID + 2L*BB*HDIM;      // 4325376

// ---------------- persistent scratch (device globals; no allocs) ----------------
__device__ float g_y0 [BB*SIN*HDIM];       // encoder layer-0 outputs   (134 MB)
__device__ float g_xp1[(long)BB*SIN*GDIM]; // precomputed y0 @ Wih1^T   (402 MB)
__device__ float g_enc[BB*SIN*HDIM];       // encoder layer-1 outputs   (134 MB)
__device__ float g_h  [2][BB*HDIM];        // running hidden states
__device__ float g_part[8*BB*GDIM];        // split-K GEMM partials     (6.3 MB)
__device__ float g_q  [BB*HDIM];
__device__ float g_att[BB*HDIM];
__device__ float g_l1 [BB*HDIM];
__device__ float g_scores[BB*SIN];
__device__ float g_aw [BB*SIN];
__device__ int   g_tok[BB];

// ---------------- software grid barrier (self-resetting; replay-safe) -----------
__device__ unsigned g_cnt = 0;
__device__ unsigned g_gen = 0;

__device__ __forceinline__ void grid_sync() {
    __threadfence();
    __syncthreads();
    if (threadIdx.x == 0) {
        unsigned gen = *(volatile unsigned*)&g_gen;
        if (atomicAdd(&g_cnt, 1u) == (unsigned)gridDim.x - 1u) {
            g_cnt = 0;
            __threadfence();
            atomicAdd(&g_gen, 1u);
        } else {
            while (*(volatile unsigned*)&g_gen == gen) __nanosleep(32);
        }
        __threadfence();
    }
    __syncthreads();
}

// ---------------- init (runs every launch) ----------------
__global__ void k_init() {
    int i = blockIdx.x*256 + threadIdx.x;      // 65536 threads
    g_h[0][i] = 0.f; g_h[1][i] = 0.f;
    if (i == 0) g_cnt = 0;
    if (i < BB) g_tok[i] = 0;
}

// ---------------- one 64x64xKlen tile (decoder path): split-K partial ------------
__device__ __forceinline__ void tile_mm(
    const float* __restrict__ A, long lda, const int* __restrict__ idx,
    const float* __restrict__ B, long ldb,
    int k0, int Klen, int n0, float* __restrict__ Cz, int N,
    float (&As)[16][68], float (&Bs)[16][68])
{
    const int tid = threadIdx.x;
    const int lr  = tid >> 2;
    const int lc  = (tid & 3) << 2;
    const int ty4 = (tid >> 4) << 2;
    const int tx4 = (tid & 15) << 2;

    long arow = idx ? (long)idx[lr]*lda : (long)lr*lda;
    const float* Ap = A + arow + k0 + lc;
    const float* Bp = B + (long)(n0 + lr)*ldb + k0 + lc;

    float acc[4][4] = {};
    float4 av = *(const float4*)Ap;
    float4 bv = *(const float4*)Bp;

    for (int kt = 0; kt < Klen; kt += 16) {
        As[lc+0][lr]=av.x; As[lc+1][lr]=av.y; As[lc+2][lr]=av.z; As[lc+3][lr]=av.w;
        Bs[lc+0][lr]=bv.x; Bs[lc+1][lr]=bv.y; Bs[lc+2][lr]=bv.z; Bs[lc+3][lr]=bv.w;
        __syncthreads();
        if (kt + 16 < Klen) {
            av = *(const float4*)(Ap + kt + 16);
            bv = *(const float4*)(Bp + kt + 16);
        }
        #pragma unroll
        for (int k = 0; k < 16; k++) {
            float4 a = *(const float4*)&As[k][ty4];
            float4 b = *(const float4*)&Bs[k][tx4];
            acc[0][0]+=a.x*b.x; acc[0][1]+=a.x*b.y; acc[0][2]+=a.x*b.z; acc[0][3]+=a.x*b.w;
            acc[1][0]+=a.y*b.x; acc[1][1]+=a.y*b.y; acc[1][2]+=a.y*b.z; acc[1][3]+=a.y*b.w;
            acc[2][0]+=a.z*b.x; acc[2][1]+=a.z*b.y; acc[2][2]+=a.z*b.z; acc[2][3]+=a.z*b.w;
            acc[3][0]+=a.w*b.x; acc[3][1]+=a.w*b.y; acc[3][2]+=a.w*b.z; acc[3][3]+=a.w*b.w;
        }
        __syncthreads();
    }
    float* Cp = Cz + (long)ty4*N + n0 + tx4;
    #pragma unroll
    for (int i = 0; i < 4; i++)
        *(float4*)(Cp + (long)i*N) = make_float4(acc[i][0],acc[i][1],acc[i][2],acc[i][3]);
}

// ---------------- persistent encoder GRU scan: weight-resident in smem ----------
// Each block owns one region: z = bid&7 (K-slice of 128), g = bid>>3 (192 N-cols).
// Whh slice (192x128) lives in shared for all 512 steps. Per step: stage A (h
// slice, 64x128) into shared, then a sync-free 128-deep k-loop, 4x12 microtile.
__global__ __launch_bounds__(256,1) void enc_scan(
    int layer, const float* __restrict__ x,
    const float* __restrict__ Wih,
    const float* __restrict__ Whh,
    const float* __restrict__ bih, const float* __restrict__ bhh)
{
    extern __shared__ float sm[];
    float* Bsh = sm;                 // [128][BPAD]
    float* Ash = sm + 128*BPAD;      // [128][EPAD]

    const int tid  = threadIdx.x;
    const int bid  = blockIdx.x;
    const int z    = bid & 7;
    const int g    = bid >> 3;       // 0..15
    const int k0   = z * 128;
    const int n0   = g * 192;
    const int nthr = gridDim.x * blockDim.x;
    const int gtid = bid * blockDim.x + tid;
    float* h = g_h[layer];
    float* dst = (layer == 0) ? g_y0 : g_enc;

    // ---- load resident B slice: Bsh[k][n] = Whh[n0+n][k0+k], once ----
    for (int i = tid; i < 192*32; i += 256) {
        int n = i % 192, kq = i / 192;            // kq: float4 index along k
        float4 v = *(const float4*)(Whh + (long)(n0+n)*1024 + k0 + kq*4);
        Bsh[(kq*4+0)*BPAD + n] = v.x;
        Bsh[(kq*4+1)*BPAD + n] = v.y;
        Bsh[(kq*4+2)*BPAD + n] = v.z;
        Bsh[(kq*4+3)*BPAD + n] = v.w;
    }

    const int ty4 = (tid >> 4) << 2;   // m base (0..60)
    const int tx4 = (tid & 15) << 2;   // n base within 64-col group
    const int am  = tid >> 2;          // A-load row (0..63)
    const int akq = tid & 3;           // A-load k-phase

    for (int t = 0; t < SIN; t++) {
        // ---- stage A: Ash[k][m] = h[m][k0+k] ----
        #pragma unroll
        for (int j = 0; j < 8; j++) {
            int kq = akq + j*4;
            float4 v = *(const float4*)(h + am*1024 + k0 + kq*4);
            Ash[(kq*4+0)*EPAD + am] = v.x;
            Ash[(kq*4+1)*EPAD + am] = v.y;
            Ash[(kq*4+2)*EPAD + am] = v.z;
            Ash[(kq*4+3)*EPAD + am] = v.w;
        }
        __syncthreads();

        // ---- sync-free compute: 64x192 tile, 4x12 microtile ----
        float acc[4][12] = {};
        #pragma unroll 8
        for (int k = 0; k < 128; k++) {
            float4 a  = *(const float4*)&Ash[k*EPAD + ty4];
            float4 b0 = *(const float4*)&Bsh[k*BPAD + tx4];
            float4 b1 = *(const float4*)&Bsh[k*BPAD + tx4 + 64];
            float4 b2 = *(const float4*)&Bsh[k*BPAD + tx4 + 128];
            acc[0][0]+=a.x*b0.x; acc[0][1]+=a.x*b0.y; acc[0][2]+=a.x*b0.z; acc[0][3]+=a.x*b0.w;
            acc[1][0]+=a.y*b0.x; acc[1][1]+=a.y*b0.y; acc[1][2]+=a.y*b0.z; acc[1][3]+=a.y*b0.w;
            acc[2][0]+=a.z*b0.x; acc[2][1]+=a.z*b0.y; acc[2][2]+=a.z*b0.z; acc[2][3]+=a.z*b0.w;
            acc[3][0]+=a.w*b0.x; acc[3][1]+=a.w*b0.y; acc[3][2]+=a.w*b0.z; acc[3][3]+=a.w*b0.w;
            acc[0][4]+=a.x*b1.x; acc[0][5]+=a.x*b1.y; acc[0][6]+=a.x*b1.z; acc[0][7]+=a.x*b1.w;
            acc[1][4]+=a.y*b1.x; acc[1][5]+=a.y*b1.y; acc[1][6]+=a.y*b1.z; acc[1][7]+=a.y*b1.w;
            acc[2][4]+=a.z*b1.x; acc[2][5]+=a.z*b1.y; acc[2][6]+=a.z*b1.z; acc[2][7]+=a.z*b1.w;
            acc[3][4]+=a.w*b1.x; acc[3][5]+=a.w*b1.y; acc[3][6]+=a.w*b1.z; acc[3][7]+=a.w*b1.w;
            acc[0][8]+=a.x*b2.x; acc[0][9]+=a.x*b2.y; acc[0][10]+=a.x*b2.z; acc[0][11]+=a.x*b2.w;
            acc[1][8]+=a.y*b2.x; acc[1][9]+=a.y*b2.y; acc[1][10]+=a.y*b2.z; acc[1][11]+=a.y*b2.w;
            acc[2][8]+=a.z*b2.x; acc[2][9]+=a.z*b2.y; acc[2][10]+=a.z*b2.z; acc[2][11]+=a.z*b2.w;
            acc[3][8]+=a.w*b2.x; acc[3][9]+=a.w*b2.y; acc[3][10]+=a.w*b2.z; acc[3][11]+=a.w*b2.w;
        }
        // ---- store partials: g_part[z][m][n0 + jj*64 + tx4] ----
        {
            float* Cz = g_part + (long)z*64*GDIM;
            #pragma unroll
            for (int i = 0; i < 4; i++) {
                float* row = Cz + (long)(ty4+i)*GDIM + n0;
                *(float4*)(row + tx4      ) = make_float4(acc[i][0],acc[i][1],acc[i][2],acc[i][3]);
                *(float4*)(row + tx4 + 64 ) = make_float4(acc[i][4],acc[i][5],acc[i][6],acc[i][7]);
                *(float4*)(row + tx4 + 128) = make_float4(acc[i][8],acc[i][9],acc[i][10],acc[i][11]);
            }
        }
        grid_sync();

        // ---- gate phase ----
        for (int i = gtid; i < BB*HDIM; i += nthr) {
            int b = i >> 10, hh = i & 1023;
            float xr, xz, xn;
            if (layer == 0) {
                float x0 = x[(b*2  )*SIN + t];
                float x1 = x[(b*2+1)*SIN + t];
                xr = x0*Wih[2*hh]          + x1*Wih[2*hh+1]          + bih[hh];
                xz = x0*Wih[2*(HDIM+hh)]   + x1*Wih[2*(HDIM+hh)+1]   + bih[HDIM+hh];
                xn = x0*Wih[2*(2*HDIM+hh)] + x1*Wih[2*(2*HDIM+hh)+1] + bih[2*HDIM+hh];
            } else {
                const float* xp = g_xp1 + (long)(b*SIN + t)*GDIM;
                xr = xp[hh]        + bih[hh];
                xz = xp[HDIM+hh]   + bih[HDIM+hh];
                xn = xp[2*HDIM+hh] + bih[2*HDIM+hh];
            }
            float hr = bhh[hh], hz = bhh[HDIM+hh], hn = bhh[2*HDIM+hh];
            #pragma unroll
            for (int zp = 0; zp < 8; zp++) {
                const float* p = g_part + (long)(zp*64 + b)*GDIM;
                hr += p[hh]; hz += p[HDIM+hh]; hn += p[2*HDIM+hh];
            }
            float r  = 1.f/(1.f + expf(-(xr+hr)));
            float zg = 1.f/(1.f + expf(-(xz+hz)));
            float n  = tanhf(xn + r*hn);
            float hnew = (1.f - zg)*n + zg*h[i];
            h[i] = hnew;
            dst[(long)(b*SIN + t)*HDIM + hh] = hnew;
        }
        grid_sync();
    }
}

// ---------------- big GEMM: xp1[32768,3072] = y0 @ Wih1^T; 128x64 tile, 8x4 micro
__global__ __launch_bounds__(256) void gemm_big(
    const float* __restrict__ A, const float* __restrict__ B,
    float* __restrict__ C, int N, int K)
{
    __shared__ float As[16*132];   // [k][m], m=128
    __shared__ float Bs[16*68];    // [k][n], n=64
    const int m0 = blockIdx.y * 128, n0 = blockIdx.x * 64;
    const int tid = threadIdx.x;
    const int lrA = tid >> 1, lcA = (tid & 1) * 8;    // A: 2 float4 per thread
    const int lrB = tid >> 2, lcB = (tid & 3) * 4;    // B: 1 float4
    const int ty8 = (tid >> 4) * 8;
    const int tx4 = (tid & 15) * 4;

    const float* Ap = A + (long)(m0 + lrA)*K + lcA;
    const float* Bp = B + (long)(n0 + lrB)*K + lcB;

    float acc[8][4] = {};
    float4 av0 = *(const float4*)Ap;
    float4 av1 = *(const float4*)(Ap + 4);
    float4 bv  = *(const float4*)Bp;

    for (int kt = 0; kt < K; kt += 16) {
        As[(lcA+0)*132+lrA]=av0.x; As[(lcA+1)*132+lrA]=av0.y;
        As[(lcA+2)*132+lrA]=av0.z; As[(lcA+3)*132+lrA]=av0.w;
        As[(lcA+4)*132+lrA]=av1.x; As[(lcA+5)*132+lrA]=av1.y;
        As[(lcA+6)*132+lrA]=av1.z; As[(lcA+7)*132+lrA]=av1.w;
        Bs[(lcB+0)*68+lrB]=bv.x;   Bs[(lcB+1)*68+lrB]=bv.y;
        Bs[(lcB+2)*68+lrB]=bv.z;   Bs[(lcB+3)*68+lrB]=bv.w;
        __syncthreads();
        if (kt + 16 < K) {
            av0 = *(const float4*)(Ap + kt + 16);
            av1 = *(const float4*)(Ap + kt + 20);
            bv  = *(const float4*)(Bp + kt + 16);
        }
        #pragma unroll
        for (int k = 0; k < 16; k++) {
            float4 a0 = *(const float4*)&As[k*132 + ty8];
            float4 a1 = *(const float4*)&As[k*132 + ty8 + 4];
            float4 b  = *(const float4*)&Bs[k*68 + tx4];
            acc[0][0]+=a0.x*b.x; acc[0][1]+=a0.x*b.y; acc[0][2]+=a0.x*b.z; acc[0][3]+=a0.x*b.w;
            acc[1][0]+=a0.y*b.x; acc[1][1]+=a0.y*b.y; acc[1][2]+=a0.y*b.z; acc[1][3]+=a0.y*b.w;
            acc[2][0]+=a0.z*b.x; acc[2][1]+=a0.z*b.y; acc[2][2]+=a0.z*b.z; acc[2][3]+=a0.z*b.w;
            acc[3][0]+=a0.w*b.x; acc[3][1]+=a0.w*b.y; acc[3][2]+=a0.w*b.z; acc[3][3]+=a0.w*b.w;
            acc[4][0]+=a1.x*b.x; acc[4][1]+=a1.x*b.y; acc[4][2]+=a1.x*b.z; acc[4][3]+=a1.x*b.w;
            acc[5][0]+=a1.y*b.x; acc[5][1]+=a1.y*b.y; acc[5][2]+=a1.y*b.z; acc[5][3]+=a1.y*b.w;
            acc[6][0]+=a1.z*b.x; acc[6][1]+=a1.z*b.y; acc[6][2]+=a1.z*b.z; acc[6][3]+=a1.z*b.w;
            acc[7][0]+=a1.w*b.x; acc[7][1]+=a1.w*b.y; acc[7][2]+=a1.w*b.z; acc[7][3]+=a1.w*b.w;
        }
        __syncthreads();
    }
    #pragma unroll
    for (int i = 0; i < 8; i++)
        *(float4*)(C + (long)(m0 + ty8 + i)*N + n0 + tx4) =
            make_float4(acc[i][0],acc[i][1],acc[i][2],acc[i][3]);
}

// ---------------- persistent decoder: all 64 greedy autoregressive steps --------
__global__ __launch_bounds__(256,2) void dec_scan(
    const float* __restrict__ emb,
    const float* __restrict__ dWih0, const float* __restrict__ dWhh0,
    const float* __restrict__ dbih0, const float* __restrict__ dbhh0,
    const float* __restrict__ dWih1, const float* __restrict__ dWhh1,
    const float* __restrict__ dbih1, const float* __restrict__ dbhh1,
    const float* __restrict__ hqW,  const float* __restrict__ hqb,
    const float* __restrict__ combW,const float* __restrict__ combb,
    const float* __restrict__ fcW,  const float* __restrict__ fcb,
    float* __restrict__ out, float* __restrict__ outAtt)
{
    __shared__ float As[16][68], Bs[16][68];
    const int tid  = threadIdx.x;
    const int nthr = gridDim.x * blockDim.x;
    const int gtid = blockIdx.x * blockDim.x + tid;
    float* h0 = g_h[0];
    float* h1 = g_h[1];

    for (int t = 0; t < TOUT; t++) {
        // ---- layer 0 GEMM: emb[tok]@Wih0^T (z 0..3) + h0@Whh0^T (z 4..7) ----
        for (int tile = blockIdx.x; tile < 128; tile += gridDim.x) {
            int z = tile >> 4, nt = tile & 15;
            if (z < 4)
                tile_mm(emb, 1024, g_tok, dWih0, 1024, z*256, 256, nt*64,
                        g_part + (long)z*64*1024, 1024, As, Bs);
            else
                tile_mm(h0, 1024, (const int*)0, dWhh0, 1024, (z-4)*256, 256, nt*64,
                        g_part + (long)z*64*1024, 1024, As, Bs);
        }
        grid_sync();
        for (int i = gtid; i < BB*HDIM; i += nthr) {
            int b = i >> 10, n = i & 1023;
            float s = dbih0[n] + dbhh0[n];
            #pragma unroll
            for (int z = 0; z < 8; z++) s += g_part[(long)(z*64 + b)*1024 + n];
            h0[i] = tanhf(s);
        }
        grid_sync();
        // ---- layer 1 GEMM ----
        for (int tile = blockIdx.x; tile < 128; tile += gridDim.x) {
            int z = tile >> 4, nt = tile & 15;
            if (z < 4)
                tile_mm(h0, 1024, (const int*)0, dWih1, 1024, z*256, 256, nt*64,
                        g_part + (long)z*64*1024, 1024, As, Bs);
            else
                tile_mm(h1, 1024, (const int*)0, dWhh1, 1024, (z-4)*256, 256, nt*64,
                        g_part + (long)z*64*1024, 1024, As, Bs);
        }
        grid_sync();
        for (int i = gtid; i < BB*HDIM; i += nthr) {
            int b = i >> 10, n = i & 1023;
            float s = dbih1[n] + dbhh1[n];
            #pragma unroll
            for (int z = 0; z < 8; z++) s += g_part[(long)(z*64 + b)*1024 + n];
            h1[i] = tanhf(s);
        }
        grid_sync();
        // ---- q = h1 @ hqW^T + hqb ----
        for (int tile = blockIdx.x; tile < 128; tile += gridDim.x) {
            int z = tile >> 4, nt = tile & 15;
            tile_mm(h1, 1024, (const int*)0, hqW, 1024, z*128, 128, nt*64,
                    g_part + (long)z*64*1024, 1024, As, Bs);
        }
        grid_sync();
        for (int i = gtid; i < BB*HDIM; i += nthr) {
            int b = i >> 10, n = i & 1023;
            float s = hqb[n];
            #pragma unroll
            for (int z = 0; z < 8; z++) s += g_part[(long)(z*64 + b)*1024 + n];
            g_q[i] = s;
        }
        grid_sync();
        // ---- scores[b,s] = enc[b,s,:] . q[b] ----
        for (int u = blockIdx.x; u < 1024; u += gridDim.x) {
            int b = u >> 4, sc = u & 15;
            float* qs = &As[0][0];
            __syncthreads();
            for (int j = tid; j < HDIM; j += 256) qs[j] = g_q[b*HDIM + j];
            __syncthreads();
            int sl = tid >> 3, kp = tid & 7;
            int s  = sc*32 + sl;
            const float* e = g_enc + (long)(b*SIN + s)*HDIM;
            float acc = 0.f;
            #pragma unroll 4
            for (int i2 = 0; i2 < 32; i2++) {
                int k = i2*32 + kp*4;
                float4 ev = *(const float4*)(e + k);
                acc += ev.x*qs[k] + ev.y*qs[k+1] + ev.z*qs[k+2] + ev.w*qs[k+3];
            }
            acc += __shfl_xor_sync(0xffffffffu, acc, 4);
            acc += __shfl_xor_sync(0xffffffffu, acc, 2);
            acc += __shfl_xor_sync(0xffffffffu, acc, 1);
            if (kp == 0) g_scores[b*SIN + s] = acc;
            __syncthreads();
        }
        grid_sync();
        // ---- softmax over s (blocks 0..63) ----
        if (blockIdx.x < 64) {
            int b = blockIdx.x;
            float* red = &As[0][0];
            float v0 = g_scores[b*SIN + tid], v1 = g_scores[b*SIN + 256 + tid];
            red[tid] = fmaxf(v0, v1); __syncthreads();
            for (int w = 128; w > 0; w >>= 1) {
                if (tid < w) red[tid] = fmaxf(red[tid], red[tid+w]);
                __syncthreads();
            }
            float mx = red[0]; __syncthreads();
            float e0 = expf(v0 - mx), e1 = expf(v1 - mx);
            red[tid] = e0 + e1; __syncthreads();
            for (int w = 128; w > 0; w >>= 1) {
                if (tid < w) red[tid] += red[tid+w];
                __syncthreads();
            }
            float inv = 1.f/red[0];
            float a0 = e0*inv, a1 = e1*inv;
            g_aw[b*SIN + tid] = a0; g_aw[b*SIN + 256 + tid] = a1;
            if (t == TOUT-1) { outAtt[b*SIN + tid] = a0; outAtt[b*SIN + 256 + tid] = a1; }
        }
        grid_sync();
        // ---- att[b,h] = sum_s aw[s]*enc[b,s,h] ----
        for (int u = blockIdx.x; u < 256; u += gridDim.x) {
            int hc = u & 3, b = u >> 2;
            float* aw = &As[0][0];
            __syncthreads();
            for (int j = tid; j < SIN; j += 256) aw[j] = g_aw[b*SIN + j];
            __syncthreads();
            int hh = hc*256 + tid;
            const float* e = g_enc + (long)b*SIN*HDIM + hh;
            float acc = 0.f;
            #pragma unroll 8
            for (int s = 0; s < SIN; s++) acc += aw[s]*e[(long)s*HDIM];
            g_att[b*HDIM + hh] = acc;
            __syncthreads();
        }
        grid_sync();
        // ---- l1 = [h1|att] @ combW^T + combb ----
        for (int tile = blockIdx.x; tile < 128; tile += gridDim.x) {
            int z = tile >> 4, nt = tile & 15;
            if (z < 4)
                tile_mm(h1, 1024, (const int*)0, combW, 2048, z*256, 256, nt*64,
                        g_part + (long)z*64*1024, 1024, As, Bs);
            else
                tile_mm(g_att, 1024, (const int*)0, combW + 1024, 2048, (z-4)*256, 256, nt*64,
                        g_part + (long)z*64*1024, 1024, As, Bs);
        }
        grid_sync();
        for (int i = gtid; i < BB*HDIM; i += nthr) {
            int b = i >> 10, n = i & 1023;
            float s = combb[n];
            #pragma unroll
            for (int z = 0; z < 8; z++) s += g_part[(long)(z*64 + b)*1024 + n];
            g_l1[i] = s;
        }
        grid_sync();
        // ---- logits = l1 @ fcW^T + fcb -> out[:, t, :] ----
        for (int tile = blockIdx.x; tile < 128; tile += gridDim.x) {
            int z = tile >> 4, nt = tile & 15;
            tile_mm(g_l1, 1024, (const int*)0, fcW, 1024, z*128, 128, nt*64,
                    g_part + (long)z*64*1024, 1024, As, Bs);
        }
        grid_sync();
        for (int i = gtid; i < BB*VDIM; i += nthr) {
            int b = i >> 10, v = i & 1023;
            float s = fcb[v];
            #pragma unroll
            for (int z = 0; z < 8; z++) s += g_part[(long)(z*64 + b)*1024 + v];
            out[(long)(b*TOUT + t)*VDIM + v] = s;
        }
        grid_sync();
        // ---- argmax (first-max ties) -> g_tok; skip on last step ----
        if (t < TOUT-1) {
            if (blockIdx.x < 64) {
                int b = blockIdx.x;
                float* sv = &As[0][0];
                int*   si = (int*)&Bs[0][0];
                const float* l = out + (long)(b*TOUT + t)*VDIM;
                float best = -3.4e38f; int bi = 0;
                #pragma unroll
                for (int j = 0; j < 4; j++) {
                    int idx = tid*4 + j;
                    float v = l[idx];
                    if (v > best) { best = v; bi = idx; }
                }
                sv[tid] = best; si[tid] = bi; __syncthreads();
                for (int w = 128; w > 0; w >>= 1) {
                    if (tid < w) {
                        float v2 = sv[tid+w]; int i2 = si[tid+w];
                        if (v2 > sv[tid] || (v2 == sv[tid] && i2 < si[tid])) {
                            sv[tid] = v2; si[tid] = i2;
                        }
                    }
                    __syncthreads();
                }
                if (tid == 0) g_tok[b] = si[0];
            }
            grid_sync();
        }
    }
}

__global__ void k_copy_hidden(float* __restrict__ out) {   // 512 x 256
    int i = blockIdx.x*256 + threadIdx.x;
    out[i] = (&g_h[0][0])[i];
}

// ---------------- host ----------------
extern "C" void kernel_launch(void* const* d_in, const int* in_sizes, int n_in,
                              void* d_out, int out_size)
{
    (void)n_in; (void)out_size;
    // in_sizes[6]: signature order -> enc_Wih1 (3145728); dict order -> dec_Wih0 (1048576)
    bool sig = (in_sizes[6] == 3145728);
    const float* x   = (const float*)d_in[0];
    const float* emb = (const float*)d_in[1];
    const float *eWih0,*eWhh0,*ebih0,*ebhh0,*eWih1,*eWhh1,*ebih1,*ebhh1;
    const float *dWih0,*dWhh0,*dbih0,*dbhh0,*dWih1,*dWhh1,*dbih1,*dbhh1;
    if (sig) {
        eWih0=(const float*)d_in[2];  eWhh0=(const float*)d_in[3];
        ebih0=(const float*)d_in[4];  ebhh0=(const float*)d_in[5];
        eWih1=(const float*)d_in[6];  eWhh1=(const float*)d_in[7];
        ebih1=(const float*)d_in[8];  ebhh1=(const float*)d_in[9];
        dWih0=(const float*)d_in[10]; dWhh0=(const float*)d_in[11];
        dbih0=(const float*)d_in[12]; dbhh0=(const float*)d_in[13];
        dWih1=(const float*)d_in[14]; dWhh1=(const float*)d_in[15];
        dbih1=(const float*)d_in[16]; dbhh1=(const float*)d_in[17];
    } else {
        eWih0=(const float*)d_in[2];  eWhh0=(const float*)d_in[3];
        ebih0=(const float*)d_in[4];  ebhh0=(const float*)d_in[5];
        dWih0=(const float*)d_in[6];  dWhh0=(const float*)d_in[7];
        dbih0=(const float*)d_in[8];  dbhh0=(const float*)d_in[9];
        eWih1=(const float*)d_in[10]; eWhh1=(const float*)d_in[11];
        ebih1=(const float*)d_in[12]; ebhh1=(const float*)d_in[13];
        dWih1=(const float*)d_in[14]; dWhh1=(const float*)d_in[15];
        dbih1=(const float*)d_in[16]; dbhh1=(const float*)d_in[17];
    }
    const float* hq_W   = (const float*)d_in[18];
    const float* hq_b   = (const float*)d_in[19];
    const float* comb_W = (const float*)d_in[20];
    const float* comb_b = (const float*)d_in[21];
    const float* fc_W   = (const float*)d_in[22];
    const float* fc_b   = (const float*)d_in[23];
    float* out = (float*)d_out;

    float *p_y0, *p_xp1;
    cudaGetSymbolAddress((void**)&p_y0,  g_y0);
    cudaGetSymbolAddress((void**)&p_xp1, g_xp1);
    cudaFuncSetAttribute(enc_scan, cudaFuncAttributeMaxDynamicSharedMemorySize, ENC_SMEM);

    k_init<<<256,256>>>();

    // encoder layer 0 (512-step scan, one node, weight-resident)
    enc_scan<<<NBLK,256,ENC_SMEM>>>(0, x, eWih0, eWhh0, ebih0, ebhh0);
    // xp1 = y0 @ Wih1^T (one big parallel GEMM, 128x64 tile)
    gemm_big<<<dim3(48,256),256>>>(p_y0, eWih1, p_xp1, GDIM, 1024);
    // encoder layer 1
    enc_scan<<<NBLK,256,ENC_SMEM>>>(1, x, eWih1, eWhh1, ebih1, ebhh1);
    // decoder (64 greedy steps, one node)
    dec_scan<<<NBLK,256>>>(emb,
                           dWih0, dWhh0, dbih0, dbhh0,
                           dWih1, dWhh1, dbih1, dbhh1,
                           hq_W, hq_b, comb_W, comb_b, fc_W, fc_b,
                           out, out + OFF_ATT);
    // hidden [2, B, H]
    k_copy_hidden<<<512,256>>>(out + OFF_HID);
}

// round 10
// speedup vs baseline: 1.2211x; 1.0389x over previous
#include <cuda_runtime.h>
#include <math.h>

#define BB   64
#define SIN  512
#define TOUT 64
#define HDIM 1024
#define VDIM 1024
#define GDIM 3072   // 3*HDIM
#define NBLK 128    // persistent-kernel grid size (co-resident, divides all phases)

#define EPAD 68     // Ash row pad (floats)
#define BPAD 196    // Bsh row pad (floats)
#define RPAD 52     // reduction row pad (floats, 16B aligned)
// dynamic smem for enc_scan: Bsh[128][BPAD] + Ash[128][EPAD] + Red[256][RPAD]
#define ENC_SMEM ((128*BPAD + 128*EPAD + 256*RPAD) * 4)

static const long OFF_HID = (long)BB*TOUT*VDIM;        // 4194304
static const long OFF_ATT = OFF_HID + 2L*BB*HDIM;      // 4325376

// ---------------- persistent scratch (device globals; no allocs) ----------------
__device__ float g_y0 [BB*SIN*HDIM];       // encoder layer-0 outputs   (134 MB)
__device__ float g_xp1[(long)BB*SIN*GDIM]; // precomputed y0 @ Wih1^T   (402 MB)
__device__ float g_enc[BB*SIN*HDIM];       // encoder layer-1 outputs   (134 MB)
__device__ float g_h  [2][BB*HDIM];        // running hidden states
__device__ float g_part[8*BB*GDIM];        // split-K GEMM partials     (6.3 MB)
__device__ float g_q  [BB*HDIM];
__device__ float g_att[BB*HDIM];
__device__ float g_l1 [BB*HDIM];
__device__ float g_scores[BB*SIN];
__device__ float g_aw [BB*SIN];
__device__ int   g_tok[BB];

// ---------------- software grid barrier (self-resetting; replay-safe) -----------
__device__ unsigned g_cnt = 0;
__device__ unsigned g_gen = 0;

__device__ __forceinline__ void grid_sync() {
    __threadfence();
    __syncthreads();
    if (threadIdx.x == 0) {
        unsigned gen = *(volatile unsigned*)&g_gen;
        if (atomicAdd(&g_cnt, 1u) == (unsigned)gridDim.x - 1u) {
            g_cnt = 0;
            __threadfence();
            atomicAdd(&g_gen, 1u);
        } else {
            while (*(volatile unsigned*)&g_gen == gen) __nanosleep(32);
        }
        __threadfence();
    }
    __syncthreads();
}

// ---------------- init (runs every launch) ----------------
__global__ void k_init() {
    int i = blockIdx.x*256 + threadIdx.x;      // 65536 threads
    g_h[0][i] = 0.f; g_h[1][i] = 0.f;
    if (i == 0) g_cnt = 0;
    if (i < BB) g_tok[i] = 0;
}

// ---------------- one 64x64xKlen tile (decoder path): split-K partial ------------
__device__ __forceinline__ void tile_mm(
    const float* __restrict__ A, long lda, const int* __restrict__ idx,
    const float* __restrict__ B, long ldb,
    int k0, int Klen, int n0, float* __restrict__ Cz, int N,
    float (&As)[16][68], float (&Bs)[16][68])
{
    const int tid = threadIdx.x;
    const int lr  = tid >> 2;
    const int lc  = (tid & 3) << 2;
    const int ty4 = (tid >> 4) << 2;
    const int tx4 = (tid & 15) << 2;

    long arow = idx ? (long)idx[lr]*lda : (long)lr*lda;
    const float* Ap = A + arow + k0 + lc;
    const float* Bp = B + (long)(n0 + lr)*ldb + k0 + lc;

    float acc[4][4] = {};
    float4 av = *(const float4*)Ap;
    float4 bv = *(const float4*)Bp;

    for (int kt = 0; kt < Klen; kt += 16) {
        As[lc+0][lr]=av.x; As[lc+1][lr]=av.y; As[lc+2][lr]=av.z; As[lc+3][lr]=av.w;
        Bs[lc+0][lr]=bv.x; Bs[lc+1][lr]=bv.y; Bs[lc+2][lr]=bv.z; Bs[lc+3][lr]=bv.w;
        __syncthreads();
        if (kt + 16 < Klen) {
            av = *(const float4*)(Ap + kt + 16);
            bv = *(const float4*)(Bp + kt + 16);
        }
        #pragma unroll
        for (int k = 0; k < 16; k++) {
            float4 a = *(const float4*)&As[k][ty4];
            float4 b = *(const float4*)&Bs[k][tx4];
            acc[0][0]+=a.x*b.x; acc[0][1]+=a.x*b.y; acc[0][2]+=a.x*b.z; acc[0][3]+=a.x*b.w;
            acc[1][0]+=a.y*b.x; acc[1][1]+=a.y*b.y; acc[1][2]+=a.y*b.z; acc[1][3]+=a.y*b.w;
            acc[2][0]+=a.z*b.x; acc[2][1]+=a.z*b.y; acc[2][2]+=a.z*b.z; acc[2][3]+=a.z*b.w;
            acc[3][0]+=a.w*b.x; acc[3][1]+=a.w*b.y; acc[3][2]+=a.w*b.z; acc[3][3]+=a.w*b.w;
        }
        __syncthreads();
    }
    float* Cp = Cz + (long)ty4*N + n0 + tx4;
    #pragma unroll
    for (int i = 0; i < 4; i++)
        *(float4*)(Cp + (long)i*N) = make_float4(acc[i][0],acc[i][1],acc[i][2],acc[i][3]);
}

// ---------------- persistent encoder GRU scan: weight-resident, k-split ----------
// Block (z = bid&7, g = bid>>3) owns 64m x 192n x 128k. Whh slice resident in
// smem. 512 threads: lower 256 accumulate k[0:64), upper 256 k[64:128), then a
// partner reduction through shared. 4x12 microtile, sync-free k loop.
__global__ __launch_bounds__(512,1) void enc_scan(
    int layer, const float* __restrict__ x,
    const float* __restrict__ Wih,
    const float* __restrict__ Whh,
    const float* __restrict__ bih, const float* __restrict__ bhh)
{
    extern __shared__ float sm[];
    float* Bsh = sm;                          // [128][BPAD]
    float* Ash = sm + 128*BPAD;               // [128][EPAD]
    float* Red = sm + 128*BPAD + 128*EPAD;    // [256][RPAD]

    const int tid  = threadIdx.x;
    const int bid  = blockIdx.x;
    const int z    = bid & 7;
    const int g    = bid >> 3;       // 0..15
    const int k0   = z * 128;
    const int n0   = g * 192;
    const int nthr = gridDim.x * blockDim.x;           // 65536
    const int gtid = bid * blockDim.x + tid;
    float* h = g_h[layer];
    float* dst = (layer == 0) ? g_y0 : g_enc;

    // ---- load resident B slice: Bsh[k][n] = Whh[n0+n][k0+k], once ----
    for (int i = tid; i < 192*32; i += 512) {
        int n = i % 192, kq = i / 192;            // kq: float4 index along k
        float4 v = *(const float4*)(Whh + (long)(n0+n)*1024 + k0 + kq*4);
        Bsh[(kq*4+0)*BPAD + n] = v.x;
        Bsh[(kq*4+1)*BPAD + n] = v.y;
        Bsh[(kq*4+2)*BPAD + n] = v.z;
        Bsh[(kq*4+3)*BPAD + n] = v.w;
    }

    const int tl  = tid & 255;
    const int kh  = tid >> 8;          // k-half: 0 or 1
    const int ty4 = (tl >> 4) << 2;    // m base (0..60)
    const int tx4 = (tl & 15) << 2;    // n base within 64-col group
    const int am  = tid >> 3;          // A-load row (0..63)
    const int akq = tid & 7;           // A-load k-phase

    for (int t = 0; t < SIN; t++) {
        // ---- stage A: Ash[k][m] = h[m][k0+k]; 512 threads, 4 float4 each ----
        #pragma unroll
        for (int j = 0; j < 4; j++) {
            int kq = akq + j*8;
            float4 v = *(const float4*)(h + am*1024 + k0 + kq*4);
            Ash[(kq*4+0)*EPAD + am] = v.x;
            Ash[(kq*4+1)*EPAD + am] = v.y;
            Ash[(kq*4+2)*EPAD + am] = v.z;
            Ash[(kq*4+3)*EPAD + am] = v.w;
        }
        __syncthreads();

        // ---- sync-free compute over this thread's k-half ----
        float acc[4][12] = {};
        const int kbeg = kh*64, kend = kbeg + 64;
        #pragma unroll 8
        for (int k = kbeg; k < kend; k++) {
            float4 a  = *(const float4*)&Ash[k*EPAD + ty4];
            float4 b0 = *(const float4*)&Bsh[k*BPAD + tx4];
            float4 b1 = *(const float4*)&Bsh[k*BPAD + tx4 + 64];
            float4 b2 = *(const float4*)&Bsh[k*BPAD + tx4 + 128];
            acc[0][0]+=a.x*b0.x; acc[0][1]+=a.x*b0.y; acc[0][2]+=a.x*b0.z; acc[0][3]+=a.x*b0.w;
            acc[1][0]+=a.y*b0.x; acc[1][1]+=a.y*b0.y; acc[1][2]+=a.y*b0.z; acc[1][3]+=a.y*b0.w;
            acc[2][0]+=a.z*b0.x; acc[2][1]+=a.z*b0.y; acc[2][2]+=a.z*b0.z; acc[2][3]+=a.z*b0.w;
            acc[3][0]+=a.w*b0.x; acc[3][1]+=a.w*b0.y; acc[3][2]+=a.w*b0.z; acc[3][3]+=a.w*b0.w;
            acc[0][4]+=a.x*b1.x; acc[0][5]+=a.x*b1.y; acc[0][6]+=a.x*b1.z; acc[0][7]+=a.x*b1.w;
            acc[1][4]+=a.y*b1.x; acc[1][5]+=a.y*b1.y; acc[1][6]+=a.y*b1.z; acc[1][7]+=a.y*b1.w;
            acc[2][4]+=a.z*b1.x; acc[2][5]+=a.z*b1.y; acc[2][6]+=a.z*b1.z; acc[2][7]+=a.z*b1.w;
            acc[3][4]+=a.w*b1.x; acc[3][5]+=a.w*b1.y; acc[3][6]+=a.w*b1.z; acc[3][7]+=a.w*b1.w;
            acc[0][8]+=a.x*b2.x; acc[0][9]+=a.x*b2.y; acc[0][10]+=a.x*b2.z; acc[0][11]+=a.x*b2.w;
            acc[1][8]+=a.y*b2.x; acc[1][9]+=a.y*b2.y; acc[1][10]+=a.y*b2.z; acc[1][11]+=a.y*b2.w;
            acc[2][8]+=a.z*b2.x; acc[2][9]+=a.z*b2.y; acc[2][10]+=a.z*b2.z; acc[2][11]+=a.z*b2.w;
            acc[3][8]+=a.w*b2.x; acc[3][9]+=a.w*b2.y; acc[3][10]+=a.w*b2.z; acc[3][11]+=a.w*b2.w;
        }

        // ---- upper half spills accs; lower half reduces and stores ----
        if (kh == 1) {
            float* r = Red + tl*RPAD;
            #pragma unroll
            for (int i = 0; i < 4; i++) {
                *(float4*)(r + i*12    ) = make_float4(acc[i][0],acc[i][1],acc[i][2],acc[i][3]);
                *(float4*)(r + i*12 + 4) = make_float4(acc[i][4],acc[i][5],acc[i][6],acc[i][7]);
                *(float4*)(r + i*12 + 8) = make_float4(acc[i][8],acc[i][9],acc[i][10],acc[i][11]);
            }
        }
        __syncthreads();
        if (kh == 0) {
            const float* r = Red + tl*RPAD;
            float* Cz = g_part + (long)z*64*GDIM;
            #pragma unroll
            for (int i = 0; i < 4; i++) {
                float4 p0 = *(const float4*)(r + i*12);
                float4 p1 = *(const float4*)(r + i*12 + 4);
                float4 p2 = *(const float4*)(r + i*12 + 8);
                float* row = Cz + (long)(ty4+i)*GDIM + n0;
                *(float4*)(row + tx4      ) = make_float4(acc[i][0]+p0.x, acc[i][1]+p0.y,
                                                          acc[i][2]+p0.z, acc[i][3]+p0.w);
                *(float4*)(row + tx4 + 64 ) = make_float4(acc[i][4]+p1.x, acc[i][5]+p1.y,
                                                          acc[i][6]+p1.z, acc[i][7]+p1.w);
                *(float4*)(row + tx4 + 128) = make_float4(acc[i][8]+p2.x, acc[i][9]+p2.y,
                                                          acc[i][10]+p2.z, acc[i][11]+p2.w);
            }
        }
        grid_sync();

        // ---- gate phase: exactly one element per thread ----
        for (int i = gtid; i < BB*HDIM; i += nthr) {
            int b = i >> 10, hh = i & 1023;
            float xr, xz, xn;
            if (layer == 0) {
                float x0 = x[(b*2  )*SIN + t];
                float x1 = x[(b*2+1)*SIN + t];
                xr = x0*Wih[2*hh]          + x1*Wih[2*hh+1]          + bih[hh];
                xz = x0*Wih[2*(HDIM+hh)]   + x1*Wih[2*(HDIM+hh)+1]   + bih[HDIM+hh];
                xn = x0*Wih[2*(2*HDIM+hh)] + x1*Wih[2*(2*HDIM+hh)+1] + bih[2*HDIM+hh];
            } else {
                const float* xp = g_xp1 + (long)(b*SIN + t)*GDIM;
                xr = xp[hh]        + bih[hh];
                xz = xp[HDIM+hh]   + bih[HDIM+hh];
                xn = xp[2*HDIM+hh] + bih[2*HDIM+hh];
            }
            float hr = bhh[hh], hz = bhh[HDIM+hh], hn = bhh[2*HDIM+hh];
            #pragma unroll
            for (int zp = 0; zp < 8; zp++) {
                const float* p = g_part + (long)(zp*64 + b)*GDIM;
                hr += p[hh]; hz += p[HDIM+hh]; hn += p[2*HDIM+hh];
            }
            float r  = 1.f/(1.f + expf(-(xr+hr)));
            float zg = 1.f/(1.f + expf(-(xz+hz)));
            float n  = tanhf(xn + r*hn);
            float hnew = (1.f - zg)*n + zg*h[i];
            h[i] = hnew;
            dst[(long)(b*SIN + t)*HDIM + hh] = hnew;
        }
        grid_sync();
    }
}

// ---------------- big GEMM: xp1 = y0 @ Wih1^T; 128x128 tile, 8x8 microtile ------
__global__ __launch_bounds__(256) void gemm_big(
    const float* __restrict__ A, const float* __restrict__ B,
    float* __restrict__ C, int N, int K)
{
    __shared__ float As[16*132];   // [k][m], m=128
    __shared__ float Bs[16*132];   // [k][n], n=128
    const int m0 = blockIdx.y * 128, n0 = blockIdx.x * 128;
    const int tid = threadIdx.x;
    const int lr  = tid >> 1, lc = (tid & 1) * 8;     // 2 float4 per thread per mat
    const int ty4 = ((tid >> 4) & 15) * 4;
    const int tx4 = (tid & 15) * 4;

    const float* Ap = A + (long)(m0 + lr)*K + lc;
    const float* Bp = B + (long)(n0 + lr)*K + lc;

    float acc[8][8] = {};
    float4 av0 = *(const float4*)Ap;
    float4 av1 = *(const float4*)(Ap + 4);
    float4 bv0 = *(const float4*)Bp;
    float4 bv1 = *(const float4*)(Bp + 4);

    for (int kt = 0; kt < K; kt += 16) {
        As[(lc+0)*132+lr]=av0.x; As[(lc+1)*132+lr]=av0.y;
        As[(lc+2)*132+lr]=av0.z; As[(lc+3)*132+lr]=av0.w;
        As[(lc+4)*132+lr]=av1.x; As[(lc+5)*132+lr]=av1.y;
        As[(lc+6)*132+lr]=av1.z; As[(lc+7)*132+lr]=av1.w;
        Bs[(lc+0)*132+lr]=bv0.x; Bs[(lc+1)*132+lr]=bv0.y;
        Bs[(lc+2)*132+lr]=bv0.z; Bs[(lc+3)*132+lr]=bv0.w;
        Bs[(lc+4)*132+lr]=bv1.x; Bs[(lc+5)*132+lr]=bv1.y;
        Bs[(lc+6)*132+lr]=bv1.z; Bs[(lc+7)*132+lr]=bv1.w;
        __syncthreads();
        if (kt + 16 < K) {
            av0 = *(const float4*)(Ap + kt + 16);
            av1 = *(const float4*)(Ap + kt + 20);
            bv0 = *(const float4*)(Bp + kt + 16);
            bv1 = *(const float4*)(Bp + kt + 20);
        }
        #pragma unroll
        for (int k = 0; k < 16; k++) {
            float4 a0 = *(const float4*)&As[k*132 + ty4];
            float4 a1 = *(const float4*)&As[k*132 + ty4 + 64];
            float4 b0 = *(const float4*)&Bs[k*132 + tx4];
            float4 b1 = *(const float4*)&Bs[k*132 + tx4 + 64];
            float am[8] = {a0.x,a0.y,a0.z,a0.w, a1.x,a1.y,a1.z,a1.w};
            float bn[8] = {b0.x,b0.y,b0.z,b0.w, b1.x,b1.y,b1.z,b1.w};
            #pragma unroll
            for (int i = 0; i < 8; i++)
                #pragma unroll
                for (int j = 0; j < 8; j++)
                    acc[i][j] += am[i]*bn[j];
        }
        __syncthreads();
    }
    #pragma unroll
    for (int ib = 0; ib < 2; ib++)
        #pragma unroll
        for (int i = 0; i < 4; i++) {
            float* row = C + (long)(m0 + ty4 + ib*64 + i)*N + n0;
            *(float4*)(row + tx4)      = make_float4(acc[ib*4+i][0],acc[ib*4+i][1],
                                                     acc[ib*4+i][2],acc[ib*4+i][3]);
            *(float4*)(row + tx4 + 64) = make_float4(acc[ib*4+i][4],acc[ib*4+i][5],
                                                     acc[ib*4+i][6],acc[ib*4+i][7]);
        }
}

// ---------------- persistent decoder: all 64 greedy autoregressive steps --------
__global__ __launch_bounds__(256,2) void dec_scan(
    const float* __restrict__ emb,
    const float* __restrict__ dWih0, const float* __restrict__ dWhh0,
    const float* __restrict__ dbih0, const float* __restrict__ dbhh0,
    const float* __restrict__ dWih1, const float* __restrict__ dWhh1,
    const float* __restrict__ dbih1, const float* __restrict__ dbhh1,
    const float* __restrict__ hqW,  const float* __restrict__ hqb,
    const float* __restrict__ combW,const float* __restrict__ combb,
    const float* __restrict__ fcW,  const float* __restrict__ fcb,
    float* __restrict__ out, float* __restrict__ outAtt)
{
    __shared__ float As[16][68], Bs[16][68];
    const int tid  = threadIdx.x;
    const int nthr = gridDim.x * blockDim.x;
    const int gtid = blockIdx.x * blockDim.x + tid;
    float* h0 = g_h[0];
    float* h1 = g_h[1];

    for (int t = 0; t < TOUT; t++) {
        // ---- layer 0 GEMM: emb[tok]@Wih0^T (z 0..3) + h0@Whh0^T (z 4..7) ----
        for (int tile = blockIdx.x; tile < 128; tile += gridDim.x) {
            int z = tile >> 4, nt = tile & 15;
            if (z < 4)
                tile_mm(emb, 1024, g_tok, dWih0, 1024, z*256, 256, nt*64,
                        g_part + (long)z*64*1024, 1024, As, Bs);
            else
                tile_mm(h0, 1024, (const int*)0, dWhh0, 1024, (z-4)*256, 256, nt*64,
                        g_part + (long)z*64*1024, 1024, As, Bs);
        }
        grid_sync();
        for (int i = gtid; i < BB*HDIM; i += nthr) {
            int b = i >> 10, n = i & 1023;
            float s = dbih0[n] + dbhh0[n];
            #pragma unroll
            for (int z = 0; z < 8; z++) s += g_part[(long)(z*64 + b)*1024 + n];
            h0[i] = tanhf(s);
        }
        grid_sync();
        // ---- layer 1 GEMM ----
        for (int tile = blockIdx.x; tile < 128; tile += gridDim.x) {
            int z = tile >> 4, nt = tile & 15;
            if (z < 4)
                tile_mm(h0, 1024, (const int*)0, dWih1, 1024, z*256, 256, nt*64,
                        g_part + (long)z*64*1024, 1024, As, Bs);
            else
                tile_mm(h1, 1024, (const int*)0, dWhh1, 1024, (z-4)*256, 256, nt*64,
                        g_part + (long)z*64*1024, 1024, As, Bs);
        }
        grid_sync();
        for (int i = gtid; i < BB*HDIM; i += nthr) {
            int b = i >> 10, n = i & 1023;
            float s = dbih1[n] + dbhh1[n];
            #pragma unroll
            for (int z = 0; z < 8; z++) s += g_part[(long)(z*64 + b)*1024 + n];
            h1[i] = tanhf(s);
        }
        grid_sync();
        // ---- q = h1 @ hqW^T + hqb ----
        for (int tile = blockIdx.x; tile < 128; tile += gridDim.x) {
            int z = tile >> 4, nt = tile & 15;
            tile_mm(h1, 1024, (const int*)0, hqW, 1024, z*128, 128, nt*64,
                    g_part + (long)z*64*1024, 1024, As, Bs);
        }
        grid_sync();
        for (int i = gtid; i < BB*HDIM; i += nthr) {
            int b = i >> 10, n = i & 1023;
            float s = hqb[n];
            #pragma unroll
            for (int z = 0; z < 8; z++) s += g_part[(long)(z*64 + b)*1024 + n];
            g_q[i] = s;
        }
        grid_sync();
        // ---- scores[b,s] = enc[b,s,:] . q[b] ----
        for (int u = blockIdx.x; u < 1024; u += gridDim.x) {
            int b = u >> 4, sc = u & 15;
            float* qs = &As[0][0];
            __syncthreads();
            for (int j = tid; j < HDIM; j += 256) qs[j] = g_q[b*HDIM + j];
            __syncthreads();
            int sl = tid >> 3, kp = tid & 7;
            int s  = sc*32 + sl;
            const float* e = g_enc + (long)(b*SIN + s)*HDIM;
            float acc = 0.f;
            #pragma unroll 4
            for (int i2 = 0; i2 < 32; i2++) {
                int k = i2*32 + kp*4;
                float4 ev = *(const float4*)(e + k);
                acc += ev.x*qs[k] + ev.y*qs[k+1] + ev.z*qs[k+2] + ev.w*qs[k+3];
            }
            acc += __shfl_xor_sync(0xffffffffu, acc, 4);
            acc += __shfl_xor_sync(0xffffffffu, acc, 2);
            acc += __shfl_xor_sync(0xffffffffu, acc, 1);
            if (kp == 0) g_scores[b*SIN + s] = acc;
            __syncthreads();
        }
        grid_sync();
        // ---- softmax over s (blocks 0..63) ----
        if (blockIdx.x < 64) {
            int b = blockIdx.x;
            float* red = &As[0][0];
            float v0 = g_scores[b*SIN + tid], v1 = g_scores[b*SIN + 256 + tid];
            red[tid] = fmaxf(v0, v1); __syncthreads();
            for (int w = 128; w > 0; w >>= 1) {
                if (tid < w) red[tid] = fmaxf(red[tid], red[tid+w]);
                __syncthreads();
            }
            float mx = red[0]; __syncthreads();
            float e0 = expf(v0 - mx), e1 = expf(v1 - mx);
            red[tid] = e0 + e1; __syncthreads();
            for (int w = 128; w > 0; w >>= 1) {
                if (tid < w) red[tid] += red[tid+w];
                __syncthreads();
            }
            float inv = 1.f/red[0];
            float a0 = e0*inv, a1 = e1*inv;
            g_aw[b*SIN + tid] = a0; g_aw[b*SIN + 256 + tid] = a1;
            if (t == TOUT-1) { outAtt[b*SIN + tid] = a0; outAtt[b*SIN + 256 + tid] = a1; }
        }
        grid_sync();
        // ---- att[b,h] = sum_s aw[s]*enc[b,s,h] ----
        for (int u = blockIdx.x; u < 256; u += gridDim.x) {
            int hc = u & 3, b = u >> 2;
            float* aw = &As[0][0];
            __syncthreads();
            for (int j = tid; j < SIN; j += 256) aw[j] = g_aw[b*SIN + j];
            __syncthreads();
            int hh = hc*256 + tid;
            const float* e = g_enc + (long)b*SIN*HDIM + hh;
            float acc = 0.f;
            #pragma unroll 8
            for (int s = 0; s < SIN; s++) acc += aw[s]*e[(long)s*HDIM];
            g_att[b*HDIM + hh] = acc;
            __syncthreads();
        }
        grid_sync();
        // ---- l1 = [h1|att] @ combW^T + combb ----
        for (int tile = blockIdx.x; tile < 128; tile += gridDim.x) {
            int z = tile >> 4, nt = tile & 15;
            if (z < 4)
                tile_mm(h1, 1024, (const int*)0, combW, 2048, z*256, 256, nt*64,
                        g_part + (long)z*64*1024, 1024, As, Bs);
            else
                tile_mm(g_att, 1024, (const int*)0, combW + 1024, 2048, (z-4)*256, 256, nt*64,
                        g_part + (long)z*64*1024, 1024, As, Bs);
        }
        grid_sync();
        for (int i = gtid; i < BB*HDIM; i += nthr) {
            int b = i >> 10, n = i & 1023;
            float s = combb[n];
            #pragma unroll
            for (int z = 0; z < 8; z++) s += g_part[(long)(z*64 + b)*1024 + n];
            g_l1[i] = s;
        }
        grid_sync();
        // ---- logits = l1 @ fcW^T + fcb -> out[:, t, :] ----
        for (int tile = blockIdx.x; tile < 128; tile += gridDim.x) {
            int z = tile >> 4, nt = tile & 15;
            tile_mm(g_l1, 1024, (const int*)0, fcW, 1024, z*128, 128, nt*64,
                    g_part + (long)z*64*1024, 1024, As, Bs);
        }
        grid_sync();
        for (int i = gtid; i < BB*VDIM; i += nthr) {
            int b = i >> 10, v = i & 1023;
            float s = fcb[v];
            #pragma unroll
            for (int z = 0; z < 8; z++) s += g_part[(long)(z*64 + b)*1024 + v];
            out[(long)(b*TOUT + t)*VDIM + v] = s;
        }
        grid_sync();
        // ---- argmax (first-max ties) -> g_tok; skip on last step ----
        if (t < TOUT-1) {
            if (blockIdx.x < 64) {
                int b = blockIdx.x;
                float* sv = &As[0][0];
                int*   si = (int*)&Bs[0][0];
                const float* l = out + (long)(b*TOUT + t)*VDIM;
                float best = -3.4e38f; int bi = 0;
                #pragma unroll
                for (int j = 0; j < 4; j++) {
                    int idx = tid*4 + j;
                    float v = l[idx];
                    if (v > best) { best = v; bi = idx; }
                }
                sv[tid] = best; si[tid] = bi; __syncthreads();
                for (int w = 128; w > 0; w >>= 1) {
                    if (tid < w) {
                        float v2 = sv[tid+w]; int i2 = si[tid+w];
                        if (v2 > sv[tid] || (v2 == sv[tid] && i2 < si[tid])) {
                            sv[tid] = v2; si[tid] = i2;
                        }
                    }
                    __syncthreads();
                }
                if (tid == 0) g_tok[b] = si[0];
            }
            grid_sync();
        }
    }
}

__global__ void k_copy_hidden(float* __restrict__ out) {   // 512 x 256
    int i = blockIdx.x*256 + threadIdx.x;
    out[i] = (&g_h[0][0])[i];
}

// ---------------- host ----------------
extern "C" void kernel_launch(void* const* d_in, const int* in_sizes, int n_in,
                              void* d_out, int out_size)
{
    (void)n_in; (void)out_size;
    // in_sizes[6]: signature order -> enc_Wih1 (3145728); dict order -> dec_Wih0 (1048576)
    bool sig = (in_sizes[6] == 3145728);
    const float* x   = (const float*)d_in[0];
    const float* emb = (const float*)d_in[1];
    const float *eWih0,*eWhh0,*ebih0,*ebhh0,*eWih1,*eWhh1,*ebih1,*ebhh1;
    const float *dWih0,*dWhh0,*dbih0,*dbhh0,*dWih1,*dWhh1,*dbih1,*dbhh1;
    if (sig) {
        eWih0=(const float*)d_in[2];  eWhh0=(const float*)d_in[3];
        ebih0=(const float*)d_in[4];  ebhh0=(const float*)d_in[5];
        eWih1=(const float*)d_in[6];  eWhh1=(const float*)d_in[7];
        ebih1=(const float*)d_in[8];  ebhh1=(const float*)d_in[9];
        dWih0=(const float*)d_in[10]; dWhh0=(const float*)d_in[11];
        dbih0=(const float*)d_in[12]; dbhh0=(const float*)d_in[13];
        dWih1=(const float*)d_in[14]; dWhh1=(const float*)d_in[15];
        dbih1=(const float*)d_in[16]; dbhh1=(const float*)d_in[17];
    } else {
        eWih0=(const float*)d_in[2];  eWhh0=(const float*)d_in[3];
        ebih0=(const float*)d_in[4];  ebhh0=(const float*)d_in[5];
        dWih0=(const float*)d_in[6];  dWhh0=(const float*)d_in[7];
        dbih0=(const float*)d_in[8];  dbhh0=(const float*)d_in[9];
        eWih1=(const float*)d_in[10]; eWhh1=(const float*)d_in[11];
        ebih1=(const float*)d_in[12]; ebhh1=(const float*)d_in[13];
        dWih1=(const float*)d_in[14]; dWhh1=(const float*)d_in[15];
        dbih1=(const float*)d_in[16]; dbhh1=(const float*)d_in[17];
    }
    const float* hq_W   = (const float*)d_in[18];
    const float* hq_b   = (const float*)d_in[19];
    const float* comb_W = (const float*)d_in[20];
    const float* comb_b = (const float*)d_in[21];
    const float* fc_W   = (const float*)d_in[22];
    const float* fc_b   = (const float*)d_in[23];
    float* out = (float*)d_out;

    float *p_y0, *p_xp1;
    cudaGetSymbolAddress((void**)&p_y0,  g_y0);
    cudaGetSymbolAddress((void**)&p_xp1, g_xp1);
    cudaFuncSetAttribute(enc_scan, cudaFuncAttributeMaxDynamicSharedMemorySize, ENC_SMEM);

    k_init<<<256,256>>>();

    // encoder layer 0 (512-step scan, one node, weight-resident, k-split)
    enc_scan<<<NBLK,512,ENC_SMEM>>>(0, x, eWih0, eWhh0, ebih0, ebhh0);
    // xp1 = y0 @ Wih1^T (one big parallel GEMM, 128x128 tile)
    gemm_big<<<dim3(24,256),256>>>(p_y0, eWih1, p_xp1, GDIM, 1024);
    // encoder layer 1
    enc_scan<<<NBLK,512,ENC_SMEM>>>(1, x, eWih1, eWhh1, ebih1, ebhh1);
    // decoder (64 greedy steps, one node)
    dec_scan<<<NBLK,256>>>(emb,
                           dWih0, dWhh0, dbih0, dbhh0,
                           dWih1, dWhh1, dbih1, dbhh1,
                           hq_W, hq_b, comb_W, comb_b, fc_W, fc_b,
                           out, out + OFF_ATT);
    // hidden [2, B, H]
    k_copy_hidden<<<512,256>>>(out + OFF_HID);
}

// round 11
// speedup vs baseline: 1.2304x; 1.0076x over previous
#include <cuda_runtime.h>
#include <math.h>

#define BB   64
#define SIN  512
#define TOUT 64
#define HDIM 1024
#define VDIM 1024
#define GDIM 3072   // 3*HDIM
#define NBLK 128    // persistent-kernel grid size (co-resident, divides all phases)

#define EPAD 68     // Ash row pad (floats)
#define BPAD 196    // Bsh row pad (floats)
// dynamic smem for enc_scan: Bsh[128][BPAD] + Ash[128][EPAD]
#define ENC_SMEM ((128*BPAD + 128*EPAD) * 4)

static const long OFF_HID = (long)BB*TOUT*VDIM;        // 4194304
static const long OFF_ATT = OFF_HID + 2L*BB*HDIM;      // 4325376

// ---------------- persistent scratch (device globals; no allocs) ----------------
__device__ float g_y0 [BB*SIN*HDIM];       // encoder layer-0 outputs   (134 MB)
__device__ float g_xp1[(long)BB*SIN*GDIM]; // precomputed y0 @ Wih1^T   (402 MB)
__device__ float g_enc[BB*SIN*HDIM];       // encoder layer-1 outputs   (134 MB)
__device__ float g_h  [2][BB*HDIM];        // running hidden states
__device__ float g_part[16*BB*GDIM];       // split-K GEMM partials     (12.6 MB)
__device__ float g_q  [BB*HDIM];
__device__ float g_att[BB*HDIM];
__device__ float g_l1 [BB*HDIM];
__device__ float g_scores[BB*SIN];
__device__ float g_aw [BB*SIN];
__device__ int   g_tok[BB];

// ---------------- hierarchical grid barrier (16 leaf counters + root) -----------
// Leaf counters live on separate 256B lines so the 128 arrivals serialize only
// 8-deep per L2 line (in parallel across 16 lines) instead of 128-deep on one.
// Root-last resets all counters BEFORE the release flip (safe: cnt2==15 proves
// every leaf add completed), fences, then bumps g_gen.
__device__ unsigned g_cnt1[16*64];   // leaf counters, stride 64 uints = 256B
__device__ unsigned g_cnt2 = 0;      // root counter
__device__ unsigned g_gen  = 0;      // generation word

__device__ __forceinline__ void grid_sync() {
    __threadfence();
    __syncthreads();
    if (threadIdx.x == 0) {
        unsigned gen = *(volatile unsigned*)&g_gen;
        unsigned grp = blockIdx.x & 15u;
        bool release = false;
        if (atomicAdd(&g_cnt1[grp*64], 1u) == 7u) {        // last of 8-block group
            if (atomicAdd(&g_cnt2, 1u) == 15u) {           // last group overall
                #pragma unroll
                for (int i = 0; i < 16; i++) g_cnt1[i*64] = 0;
                g_cnt2 = 0;
                __threadfence();
                atomicAdd(&g_gen, 1u);
                release = true;
            }
        }
        if (!release)
            while (*(volatile unsigned*)&g_gen == gen) __nanosleep(20);
        __threadfence();
    }
    __syncthreads();
}

// ---------------- init (runs every launch) ----------------
__global__ void k_init() {
    int i = blockIdx.x*256 + threadIdx.x;      // 65536 threads
    g_h[0][i] = 0.f; g_h[1][i] = 0.f;
    if (i == 0) { g_cnt2 = 0; g_gen = 0; }
    if (i < 16*64) g_cnt1[i] = 0;
    if (i < BB) g_tok[i] = 0;
}

// ---------------- one 64x64xKlen tile (decoder path): split-K partial ------------
__device__ __forceinline__ void tile_mm(
    const float* __restrict__ A, long lda, const int* __restrict__ idx,
    const float* __restrict__ B, long ldb,
    int k0, int Klen, int n0, float* __restrict__ Cz, int N,
    float (&As)[16][68], float (&Bs)[16][68])
{
    const int tid = threadIdx.x;
    const int lr  = tid >> 2;
    const int lc  = (tid & 3) << 2;
    const int ty4 = (tid >> 4) << 2;
    const int tx4 = (tid & 15) << 2;

    long arow = idx ? (long)idx[lr]*lda : (long)lr*lda;
    const float* Ap = A + arow + k0 + lc;
    const float* Bp = B + (long)(n0 + lr)*ldb + k0 + lc;

    float acc[4][4] = {};
    float4 av = *(const float4*)Ap;
    float4 bv = *(const float4*)Bp;

    for (int kt = 0; kt < Klen; kt += 16) {
        As[lc+0][lr]=av.x; As[lc+1][lr]=av.y; As[lc+2][lr]=av.z; As[lc+3][lr]=av.w;
        Bs[lc+0][lr]=bv.x; Bs[lc+1][lr]=bv.y; Bs[lc+2][lr]=bv.z; Bs[lc+3][lr]=bv.w;
        __syncthreads();
        if (kt + 16 < Klen) {
            av = *(const float4*)(Ap + kt + 16);
            bv = *(const float4*)(Bp + kt + 16);
        }
        #pragma unroll
        for (int k = 0; k < 16; k++) {
            float4 a = *(const float4*)&As[k][ty4];
            float4 b = *(const float4*)&Bs[k][tx4];
            acc[0][0]+=a.x*b.x; acc[0][1]+=a.x*b.y; acc[0][2]+=a.x*b.z; acc[0][3]+=a.x*b.w;
            acc[1][0]+=a.y*b.x; acc[1][1]+=a.y*b.y; acc[1][2]+=a.y*b.z; acc[1][3]+=a.y*b.w;
            acc[2][0]+=a.z*b.x; acc[2][1]+=a.z*b.y; acc[2][2]+=a.z*b.z; acc[2][3]+=a.z*b.w;
            acc[3][0]+=a.w*b.x; acc[3][1]+=a.w*b.y; acc[3][2]+=a.w*b.z; acc[3][3]+=a.w*b.w;
        }
        __syncthreads();
    }
    float* Cp = Cz + (long)ty4*N + n0 + tx4;
    #pragma unroll
    for (int i = 0; i < 4; i++)
        *(float4*)(Cp + (long)i*N) = make_float4(acc[i][0],acc[i][1],acc[i][2],acc[i][3]);
}

// ---------------- persistent encoder GRU scan: weight-resident, k-split ----------
// Block (z = bid&7, g = bid>>3) owns 64m x 192n x 128k. Whh slice resident in
// smem. 512 threads: lower 256 accumulate k[0:64) -> partial slot 2z, upper 256
// k[64:128) -> slot 2z+1. Both halves store directly (no smem reduce). Gate
// phase sums all 16 slots in increasing-k order.
__global__ __launch_bounds__(512,1) void enc_scan(
    int layer, const float* __restrict__ x,
    const float* __restrict__ Wih,
    const float* __restrict__ Whh,
    const float* __restrict__ bih, const float* __restrict__ bhh)
{
    extern __shared__ float sm[];
    float* Bsh = sm;                          // [128][BPAD]
    float* Ash = sm + 128*BPAD;               // [128][EPAD]

    const int tid  = threadIdx.x;
    const int bid  = blockIdx.x;
    const int z    = bid & 7;
    const int g    = bid >> 3;       // 0..15
    const int k0   = z * 128;
    const int n0   = g * 192;
    const int nthr = gridDim.x * blockDim.x;           // 65536
    const int gtid = bid * blockDim.x + tid;
    float* h = g_h[layer];
    float* dst = (layer == 0) ? g_y0 : g_enc;

    // ---- load resident B slice: Bsh[k][n] = Whh[n0+n][k0+k], once ----
    for (int i = tid; i < 192*32; i += 512) {
        int n = i % 192, kq = i / 192;            // kq: float4 index along k
        float4 v = *(const float4*)(Whh + (long)(n0+n)*1024 + k0 + kq*4);
        Bsh[(kq*4+0)*BPAD + n] = v.x;
        Bsh[(kq*4+1)*BPAD + n] = v.y;
        Bsh[(kq*4+2)*BPAD + n] = v.z;
        Bsh[(kq*4+3)*BPAD + n] = v.w;
    }

    const int tl  = tid & 255;
    const int kh  = tid >> 8;          // k-half: 0 or 1
    const int ty4 = (tl >> 4) << 2;    // m base (0..60)
    const int tx4 = (tl & 15) << 2;    // n base within 64-col group
    const int am  = tid >> 3;          // A-load row (0..63)
    const int akq = tid & 7;           // A-load k-phase
    float* Cz = g_part + (long)(2*z + kh)*64*GDIM;

    for (int t = 0; t < SIN; t++) {
        // ---- stage A: Ash[k][m] = h[m][k0+k]; 512 threads, 4 float4 each ----
        #pragma unroll
        for (int j = 0; j < 4; j++) {
            int kq = akq + j*8;
            float4 v = *(const float4*)(h + am*1024 + k0 + kq*4);
            Ash[(kq*4+0)*EPAD + am] = v.x;
            Ash[(kq*4+1)*EPAD + am] = v.y;
            Ash[(kq*4+2)*EPAD + am] = v.z;
            Ash[(kq*4+3)*EPAD + am] = v.w;
        }
        __syncthreads();

        // ---- sync-free compute over this thread's k-half ----
        float acc[4][12] = {};
        const int kbeg = kh*64, kend = kbeg + 64;
        #pragma unroll 8
        for (int k = kbeg; k < kend; k++) {
            float4 a  = *(const float4*)&Ash[k*EPAD + ty4];
            float4 b0 = *(const float4*)&Bsh[k*BPAD + tx4];
            float4 b1 = *(const float4*)&Bsh[k*BPAD + tx4 + 64];
            float4 b2 = *(const float4*)&Bsh[k*BPAD + tx4 + 128];
            acc[0][0]+=a.x*b0.x; acc[0][1]+=a.x*b0.y; acc[0][2]+=a.x*b0.z; acc[0][3]+=a.x*b0.w;
            acc[1][0]+=a.y*b0.x; acc[1][1]+=a.y*b0.y; acc[1][2]+=a.y*b0.z; acc[1][3]+=a.y*b0.w;
            acc[2][0]+=a.z*b0.x; acc[2][1]+=a.z*b0.y; acc[2][2]+=a.z*b0.z; acc[2][3]+=a.z*b0.w;
            acc[3][0]+=a.w*b0.x; acc[3][1]+=a.w*b0.y; acc[3][2]+=a.w*b0.z; acc[3][3]+=a.w*b0.w;
            acc[0][4]+=a.x*b1.x; acc[0][5]+=a.x*b1.y; acc[0][6]+=a.x*b1.z; acc[0][7]+=a.x*b1.w;
            acc[1][4]+=a.y*b1.x; acc[1][5]+=a.y*b1.y; acc[1][6]+=a.y*b1.z; acc[1][7]+=a.y*b1.w;
            acc[2][4]+=a.z*b1.x; acc[2][5]+=a.z*b1.y; acc[2][6]+=a.z*b1.z; acc[2][7]+=a.z*b1.w;
            acc[3][4]+=a.w*b1.x; acc[3][5]+=a.w*b1.y; acc[3][6]+=a.w*b1.z; acc[3][7]+=a.w*b1.w;
            acc[0][8]+=a.x*b2.x; acc[0][9]+=a.x*b2.y; acc[0][10]+=a.x*b2.z; acc[0][11]+=a.x*b2.w;
            acc[1][8]+=a.y*b2.x; acc[1][9]+=a.y*b2.y; acc[1][10]+=a.y*b2.z; acc[1][11]+=a.y*b2.w;
            acc[2][8]+=a.z*b2.x; acc[2][9]+=a.z*b2.y; acc[2][10]+=a.z*b2.z; acc[2][11]+=a.z*b2.w;
            acc[3][8]+=a.w*b2.x; acc[3][9]+=a.w*b2.y; acc[3][10]+=a.w*b2.z; acc[3][11]+=a.w*b2.w;
        }

        // ---- both halves store their own partial slot directly ----
        #pragma unroll
        for (int i = 0; i < 4; i++) {
            float* row = Cz + (long)(ty4+i)*GDIM + n0;
            *(float4*)(row + tx4      ) = make_float4(acc[i][0],acc[i][1],acc[i][2],acc[i][3]);
            *(float4*)(row + tx4 + 64 ) = make_float4(acc[i][4],acc[i][5],acc[i][6],acc[i][7]);
            *(float4*)(row + tx4 + 128) = make_float4(acc[i][8],acc[i][9],acc[i][10],acc[i][11]);
        }
        grid_sync();

        // ---- gate phase: exactly one element per thread ----
        for (int i = gtid; i < BB*HDIM; i += nthr) {
            int b = i >> 10, hh = i & 1023;
            float xr, xz, xn;
            if (layer == 0) {
                float x0 = x[(b*2  )*SIN + t];
                float x1 = x[(b*2+1)*SIN + t];
                xr = x0*Wih[2*hh]          + x1*Wih[2*hh+1]          + bih[hh];
                xz = x0*Wih[2*(HDIM+hh)]   + x1*Wih[2*(HDIM+hh)+1]   + bih[HDIM+hh];
                xn = x0*Wih[2*(2*HDIM+hh)] + x1*Wih[2*(2*HDIM+hh)+1] + bih[2*HDIM+hh];
            } else {
                const float* xp = g_xp1 + (long)(b*SIN + t)*GDIM;
                xr = xp[hh]        + bih[hh];
                xz = xp[HDIM+hh]   + bih[HDIM+hh];
                xn = xp[2*HDIM+hh] + bih[2*HDIM+hh];
            }
            float hr = bhh[hh], hz = bhh[HDIM+hh], hn = bhh[2*HDIM+hh];
            #pragma unroll
            for (int zp = 0; zp < 16; zp++) {
                const float* p = g_part + (long)(zp*64 + b)*GDIM;
                hr += p[hh]; hz += p[HDIM+hh]; hn += p[2*HDIM+hh];
            }
            float r  = 1.f/(1.f + expf(-(xr+hr)));
            float zg = 1.f/(1.f + expf(-(xz+hz)));
            float n  = tanhf(xn + r*hn);
            float hnew = (1.f - zg)*n + zg*h[i];
            h[i] = hnew;
            dst[(long)(b*SIN + t)*HDIM + hh] = hnew;
        }
        grid_sync();
    }
}

// ---------------- big GEMM: xp1 = y0 @ Wih1^T; 128x128 tile, 8x8 microtile ------
__global__ __launch_bounds__(256) void gemm_big(
    const float* __restrict__ A, const float* __restrict__ B,
    float* __restrict__ C, int N, int K)
{
    __shared__ float As[16*132];   // [k][m], m=128
    __shared__ float Bs[16*132];   // [k][n], n=128
    const int m0 = blockIdx.y * 128, n0 = blockIdx.x * 128;
    const int tid = threadIdx.x;
    const int lr  = tid >> 1, lc = (tid & 1) * 8;     // 2 float4 per thread per mat
    const int ty4 = ((tid >> 4) & 15) * 4;
    const int tx4 = (tid & 15) * 4;

    const float* Ap = A + (long)(m0 + lr)*K + lc;
    const float* Bp = B + (long)(n0 + lr)*K + lc;

    float acc[8][8] = {};
    float4 av0 = *(const float4*)Ap;
    float4 av1 = *(const float4*)(Ap + 4);
    float4 bv0 = *(const float4*)Bp;
    float4 bv1 = *(const float4*)(Bp + 4);

    for (int kt = 0; kt < K; kt += 16) {
        As[(lc+0)*132+lr]=av0.x; As[(lc+1)*132+lr]=av0.y;
        As[(lc+2)*132+lr]=av0.z; As[(lc+3)*132+lr]=av0.w;
        As[(lc+4)*132+lr]=av1.x; As[(lc+5)*132+lr]=av1.y;
        As[(lc+6)*132+lr]=av1.z; As[(lc+7)*132+lr]=av1.w;
        Bs[(lc+0)*132+lr]=bv0.x; Bs[(lc+1)*132+lr]=bv0.y;
        Bs[(lc+2)*132+lr]=bv0.z; Bs[(lc+3)*132+lr]=bv0.w;
        Bs[(lc+4)*132+lr]=bv1.x; Bs[(lc+5)*132+lr]=bv1.y;
        Bs[(lc+6)*132+lr]=bv1.z; Bs[(lc+7)*132+lr]=bv1.w;
        __syncthreads();
        if (kt + 16 < K) {
            av0 = *(const float4*)(Ap + kt + 16);
            av1 = *(const float4*)(Ap + kt + 20);
            bv0 = *(const float4*)(Bp + kt + 16);
            bv1 = *(const float4*)(Bp + kt + 20);
        }
        #pragma unroll
        for (int k = 0; k < 16; k++) {
            float4 a0 = *(const float4*)&As[k*132 + ty4];
            float4 a1 = *(const float4*)&As[k*132 + ty4 + 64];
            float4 b0 = *(const float4*)&Bs[k*132 + tx4];
            float4 b1 = *(const float4*)&Bs[k*132 + tx4 + 64];
            float am[8] = {a0.x,a0.y,a0.z,a0.w, a1.x,a1.y,a1.z,a1.w};
            float bn[8] = {b0.x,b0.y,b0.z,b0.w, b1.x,b1.y,b1.z,b1.w};
            #pragma unroll
            for (int i = 0; i < 8; i++)
                #pragma unroll
                for (int j = 0; j < 8; j++)
                    acc[i][j] += am[i]*bn[j];
        }
        __syncthreads();
    }
    #pragma unroll
    for (int ib = 0; ib < 2; ib++)
        #pragma unroll
        for (int i = 0; i < 4; i++) {
            float* row = C + (long)(m0 + ty4 + ib*64 + i)*N + n0;
            *(float4*)(row + tx4)      = make_float4(acc[ib*4+i][0],acc[ib*4+i][1],
                                                     acc[ib*4+i][2],acc[ib*4+i][3]);
            *(float4*)(row + tx4 + 64) = make_float4(acc[ib*4+i][4],acc[ib*4+i][5],
                                                     acc[ib*4+i][6],acc[ib*4+i][7]);
        }
}

// ---------------- persistent decoder: all 64 greedy autoregressive steps --------
__global__ __launch_bounds__(256,2) void dec_scan(
    const float* __restrict__ emb,
    const float* __restrict__ dWih0, const float* __restrict__ dWhh0,
    const float* __restrict__ dbih0, const float* __restrict__ dbhh0,
    const float* __restrict__ dWih1, const float* __restrict__ dWhh1,
    const float* __restrict__ dbih1, const float* __restrict__ dbhh1,
    const float* __restrict__ hqW,  const float* __restrict__ hqb,
    const float* __restrict__ combW,const float* __restrict__ combb,
    const float* __restrict__ fcW,  const float* __restrict__ fcb,
    float* __restrict__ out, float* __restrict__ outAtt)
{
    __shared__ float As[16][68], Bs[16][68];
    const int tid  = threadIdx.x;
    const int nthr = gridDim.x * blockDim.x;
    const int gtid = blockIdx.x * blockDim.x + tid;
    float* h0 = g_h[0];
    float* h1 = g_h[1];

    for (int t = 0; t < TOUT; t++) {
        // ---- layer 0 GEMM: emb[tok]@Wih0^T (z 0..3) + h0@Whh0^T (z 4..7) ----
        for (int tile = blockIdx.x; tile < 128; tile += gridDim.x) {
            int z = tile >> 4, nt = tile & 15;
            if (z < 4)
                tile_mm(emb, 1024, g_tok, dWih0, 1024, z*256, 256, nt*64,
                        g_part + (long)z*64*1024, 1024, As, Bs);
            else
                tile_mm(h0, 1024, (const int*)0, dWhh0, 1024, (z-4)*256, 256, nt*64,
                        g_part + (long)z*64*1024, 1024, As, Bs);
        }
        grid_sync();
        for (int i = gtid; i < BB*HDIM; i += nthr) {
            int b = i >> 10, n = i & 1023;
            float s = dbih0[n] + dbhh0[n];
            #pragma unroll
            for (int z = 0; z < 8; z++) s += g_part[(long)(z*64 + b)*1024 + n];
            h0[i] = tanhf(s);
        }
        grid_sync();
        // ---- layer 1 GEMM ----
        for (int tile = blockIdx.x; tile < 128; tile += gridDim.x) {
            int z = tile >> 4, nt = tile & 15;
            if (z < 4)
                tile_mm(h0, 1024, (const int*)0, dWih1, 1024, z*256, 256, nt*64,
                        g_part + (long)z*64*1024, 1024, As, Bs);
            else
                tile_mm(h1, 1024, (const int*)0, dWhh1, 1024, (z-4)*256, 256, nt*64,
                        g_part + (long)z*64*1024, 1024, As, Bs);
        }
        grid_sync();
        for (int i = gtid; i < BB*HDIM; i += nthr) {
            int b = i >> 10, n = i & 1023;
            float s = dbih1[n] + dbhh1[n];
            #pragma unroll
            for (int z = 0; z < 8; z++) s += g_part[(long)(z*64 + b)*1024 + n];
            h1[i] = tanhf(s);
        }
        grid_sync();
        // ---- q = h1 @ hqW^T + hqb ----
        for (int tile = blockIdx.x; tile < 128; tile += gridDim.x) {
            int z = tile >> 4, nt = tile & 15;
            tile_mm(h1, 1024, (const int*)0, hqW, 1024, z*128, 128, nt*64,
                    g_part + (long)z*64*1024, 1024, As, Bs);
        }
        grid_sync();
        for (int i = gtid; i < BB*HDIM; i += nthr) {
            int b = i >> 10, n = i & 1023;
            float s = hqb[n];
            #pragma unroll
            for (int z = 0; z < 8; z++) s += g_part[(long)(z*64 + b)*1024 + n];
            g_q[i] = s;
        }
        grid_sync();
        // ---- scores[b,s] = enc[b,s,:] . q[b] ----
        for (int u = blockIdx.x; u < 1024; u += gridDim.x) {
            int b = u >> 4, sc = u & 15;
            float* qs = &As[0][0];
            __syncthreads();
            for (int j = tid; j < HDIM; j += 256) qs[j] = g_q[b*HDIM + j];
            __syncthreads();
            int sl = tid >> 3, kp = tid & 7;
            int s  = sc*32 + sl;
            const float* e = g_enc + (long)(b*SIN + s)*HDIM;
            float acc = 0.f;
            #pragma unroll 4
            for (int i2 = 0; i2 < 32; i2++) {
                int k = i2*32 + kp*4;
                float4 ev = *(const float4*)(e + k);
                acc += ev.x*qs[k] + ev.y*qs[k+1] + ev.z*qs[k+2] + ev.w*qs[k+3];
            }
            acc += __shfl_xor_sync(0xffffffffu, acc, 4);
            acc += __shfl_xor_sync(0xffffffffu, acc, 2);
            acc += __shfl_xor_sync(0xffffffffu, acc, 1);
            if (kp == 0) g_scores[b*SIN + s] = acc;
            __syncthreads();
        }
        grid_sync();
        // ---- softmax over s (blocks 0..63) ----
        if (blockIdx.x < 64) {
            int b = blockIdx.x;
            float* red = &As[0][0];
            float v0 = g_scores[b*SIN + tid], v1 = g_scores[b*SIN + 256 + tid];
            red[tid] = fmaxf(v0, v1); __syncthreads();
            for (int w = 128; w > 0; w >>= 1) {
                if (tid < w) red[tid] = fmaxf(red[tid], red[tid+w]);
                __syncthreads();
            }
            float mx = red[0]; __syncthreads();
            float e0 = expf(v0 - mx), e1 = expf(v1 - mx);
            red[tid] = e0 + e1; __syncthreads();
            for (int w = 128; w > 0; w >>= 1) {
                if (tid < w) red[tid] += red[tid+w];
                __syncthreads();
            }
            float inv = 1.f/red[0];
            float a0 = e0*inv, a1 = e1*inv;
            g_aw[b*SIN + tid] = a0; g_aw[b*SIN + 256 + tid] = a1;
            if (t == TOUT-1) { outAtt[b*SIN + tid] = a0; outAtt[b*SIN + 256 + tid] = a1; }
        }
        grid_sync();
        // ---- att[b,h] = sum_s aw[s]*enc[b,s,h] ----
        for (int u = blockIdx.x; u < 256; u += gridDim.x) {
            int hc = u & 3, b = u >> 2;
            float* aw = &As[0][0];
            __syncthreads();
            for (int j = tid; j < SIN; j += 256) aw[j] = g_aw[b*SIN + j];
            __syncthreads();
            int hh = hc*256 + tid;
            const float* e = g_enc + (long)b*SIN*HDIM + hh;
            float acc = 0.f;
            #pragma unroll 8
            for (int s = 0; s < SIN; s++) acc += aw[s]*e[(long)s*HDIM];
            g_att[b*HDIM + hh] = acc;
            __syncthreads();
        }
        grid_sync();
        // ---- l1 = [h1|att] @ combW^T + combb ----
        for (int tile = blockIdx.x; tile < 128; tile += gridDim.x) {
            int z = tile >> 4, nt = tile & 15;
            if (z < 4)
                tile_mm(h1, 1024, (const int*)0, combW, 2048, z*256, 256, nt*64,
                        g_part + (long)z*64*1024, 1024, As, Bs);
            else
                tile_mm(g_att, 1024, (const int*)0, combW + 1024, 2048, (z-4)*256, 256, nt*64,
                        g_part + (long)z*64*1024, 1024, As, Bs);
        }
        grid_sync();
        for (int i = gtid; i < BB*HDIM; i += nthr) {
            int b = i >> 10, n = i & 1023;
            float s = combb[n];
            #pragma unroll
            for (int z = 0; z < 8; z++) s += g_part[(long)(z*64 + b)*1024 + n];
            g_l1[i] = s;
        }
        grid_sync();
        // ---- logits = l1 @ fcW^T + fcb -> out[:, t, :] ----
        for (int tile = blockIdx.x; tile < 128; tile += gridDim.x) {
            int z = tile >> 4, nt = tile & 15;
            tile_mm(g_l1, 1024, (const int*)0, fcW, 1024, z*128, 128, nt*64,
                    g_part + (long)z*64*1024, 1024, As, Bs);
        }
        grid_sync();
        for (int i = gtid; i < BB*VDIM; i += nthr) {
            int b = i >> 10, v = i & 1023;
            float s = fcb[v];
            #pragma unroll
            for (int z = 0; z < 8; z++) s += g_part[(long)(z*64 + b)*1024 + v];
            out[(long)(b*TOUT + t)*VDIM + v] = s;
        }
        grid_sync();
        // ---- argmax (first-max ties) -> g_tok; skip on last step ----
        if (t < TOUT-1) {
            if (blockIdx.x < 64) {
                int b = blockIdx.x;
                float* sv = &As[0][0];
                int*   si = (int*)&Bs[0][0];
                const float* l = out + (long)(b*TOUT + t)*VDIM;
                float best = -3.4e38f; int bi = 0;
                #pragma unroll
                for (int j = 0; j < 4; j++) {
                    int idx = tid*4 + j;
                    float v = l[idx];
                    if (v > best) { best = v; bi = idx; }
                }
                sv[tid] = best; si[tid] = bi; __syncthreads();
                for (int w = 128; w > 0; w >>= 1) {
                    if (tid < w) {
                        float v2 = sv[tid+w]; int i2 = si[tid+w];
                        if (v2 > sv[tid] || (v2 == sv[tid] && i2 < si[tid])) {
                            sv[tid] = v2; si[tid] = i2;
                        }
                    }
                    __syncthreads();
                }
                if (tid == 0) g_tok[b] = si[0];
            }
            grid_sync();
        }
    }
}

__global__ void k_copy_hidden(float* __restrict__ out) {   // 512 x 256
    int i = blockIdx.x*256 + threadIdx.x;
    out[i] = (&g_h[0][0])[i];
}

// ---------------- host ----------------
extern "C" void kernel_launch(void* const* d_in, const int* in_sizes, int n_in,
                              void* d_out, int out_size)
{
    (void)n_in; (void)out_size;
    // in_sizes[6]: signature order -> enc_Wih1 (3145728); dict order -> dec_Wih0 (1048576)
    bool sig = (in_sizes[6] == 3145728);
    const float* x   = (const float*)d_in[0];
    const float* emb = (const float*)d_in[1];
    const float *eWih0,*eWhh0,*ebih0,*ebhh0,*eWih1,*eWhh1,*ebih1,*ebhh1;
    const float *dWih0,*dWhh0,*dbih0,*dbhh0,*dWih1,*dWhh1,*dbih1,*dbhh1;
    if (sig) {
        eWih0=(const float*)d_in[2];  eWhh0=(const float*)d_in[3];
        ebih0=(const float*)d_in[4];  ebhh0=(const float*)d_in[5];
        eWih1=(const float*)d_in[6];  eWhh1=(const float*)d_in[7];
        ebih1=(const float*)d_in[8];  ebhh1=(const float*)d_in[9];
        dWih0=(const float*)d_in[10]; dWhh0=(const float*)d_in[11];
        dbih0=(const float*)d_in[12]; dbhh0=(const float*)d_in[13];
        dWih1=(const float*)d_in[14]; dWhh1=(const float*)d_in[15];
        dbih1=(const float*)d_in[16]; dbhh1=(const float*)d_in[17];
    } else {
        eWih0=(const float*)d_in[2];  eWhh0=(const float*)d_in[3];
        ebih0=(const float*)d_in[4];  ebhh0=(const float*)d_in[5];
        dWih0=(const float*)d_in[6];  dWhh0=(const float*)d_in[7];
        dbih0=(const float*)d_in[8];  dbhh0=(const float*)d_in[9];
        eWih1=(const float*)d_in[10]; eWhh1=(const float*)d_in[11];
        ebih1=(const float*)d_in[12]; ebhh1=(const float*)d_in[13];
        dWih1=(const float*)d_in[14]; dWhh1=(const float*)d_in[15];
        dbih1=(const float*)d_in[16]; dbhh1=(const float*)d_in[17];
    }
    const float* hq_W   = (const float*)d_in[18];
    const float* hq_b   = (const float*)d_in[19];
    const float* comb_W = (const float*)d_in[20];
    const float* comb_b = (const float*)d_in[21];
    const float* fc_W   = (const float*)d_in[22];
    const float* fc_b   = (const float*)d_in[23];
    float* out = (float*)d_out;

    float *p_y0, *p_xp1;
    cudaGetSymbolAddress((void**)&p_y0,  g_y0);
    cudaGetSymbolAddress((void**)&p_xp1, g_xp1);
    cudaFuncSetAttribute(enc_scan, cudaFuncAttributeMaxDynamicSharedMemorySize, ENC_SMEM);

    k_init<<<256,256>>>();

    // encoder layer 0 (512-step scan, one node, weight-resident, k-split)
    enc_scan<<<NBLK,512,ENC_SMEM>>>(0, x, eWih0, eWhh0, ebih0, ebhh0);
    // xp1 = y0 @ Wih1^T (one big parallel GEMM, 128x128 tile)
    gemm_big<<<dim3(24,256),256>>>(p_y0, eWih1, p_xp1, GDIM, 1024);
    // encoder layer 1
    enc_scan<<<NBLK,512,ENC_SMEM>>>(1, x, eWih1, eWhh1, ebih1, ebhh1);
    // decoder (64 greedy steps, one node)
    dec_scan<<<NBLK,256>>>(emb,
                           dWih0, dWhh0, dbih0, dbhh0,
                           dWih1, dWhh1, dbih1, dbhh1,
                           hq_W, hq_b, comb_W, comb_b, fc_W, fc_b,
                           out, out + OFF_ATT);
    // hidden [2, B, H]
    k_copy_hidden<<<512,256>>>(out + OFF_HID);
}